// round 10
// baseline (speedup 1.0000x reference)
#include <cuda_runtime.h>
#include <cuda_bf16.h>
#include <cstdint>

#define NN 4096
#define HH 4

// ---------------- scratch ----------------
__device__ float  g_h1 [NN * 512];
__device__ float  g_x1 [NN * 512];
__device__ float  g_y1 [NN * 64];
__device__ float  g_x2 [NN * 64];
__device__ float  g_h2 [NN * 128];
__device__ float  g_x3 [NN * 128];
__device__ float  g_y2 [NN * 16];
__device__ float2 g_rowc1[HH * NN];   // {e^es, e^{0.2es}}
__device__ float2 g_evq1 [HH * NN];   // {e^ed, e^{0.2ed}}
__device__ float2 g_rowc2[HH * NN];
__device__ float2 g_evq2 [HH * NN];
__device__ unsigned g_adjbits[NN * (NN / 32)];
__device__ float  g_stats[256];
__device__ float  g_part [4 * NN * 128];   // attn2 partial numerators (4 j-splits)
__device__ float  g_dpart[4 * HH * NN];    // attn2 partial denominators

// ---------------- helpers ----------------
__device__ __forceinline__ unsigned smem_u32(const void* p) {
    return (unsigned)__cvta_generic_to_shared(p);
}
#define CP_ASYNC16(dst, src) \
    asm volatile("cp.async.cg.shared.global [%0], [%1], 16;" :: "r"(dst), "l"(src))
#define CP_ASYNC8(dst, src) \
    asm volatile("cp.async.ca.shared.global [%0], [%1], 8;" :: "r"(dst), "l"(src))
#define CP_COMMIT() asm volatile("cp.async.commit_group;")
#define CP_WAIT1()  asm volatile("cp.async.wait_group 1;")
#define CP_WAIT0()  asm volatile("cp.async.wait_group 0;")

#define MMA_TF32(acc, a0, a1, a2, a3, b0, b1)                                   \
    asm volatile(                                                               \
        "mma.sync.aligned.m16n8k8.row.col.f32.tf32.tf32.f32 "                   \
        "{%0,%1,%2,%3}, {%4,%5,%6,%7}, {%8,%9}, {%0,%1,%2,%3};"                 \
        : "+f"(acc[0]), "+f"(acc[1]), "+f"(acc[2]), "+f"(acc[3])                \
        : "r"(a0), "r"(a1), "r"(a2), "r"(a3), "r"(b0), "r"(b1))

__device__ __forceinline__ void split_tf32(float v, unsigned& h, unsigned& l) {
    unsigned hv;
    asm("cvt.rna.tf32.f32 %0, %1;" : "=r"(hv) : "f"(v));
    float lo = v - __uint_as_float(hv);
    unsigned lv;
    asm("cvt.rna.tf32.f32 %0, %1;" : "=r"(lv) : "f"(lo));
    h = hv; l = lv;
}

// ---------------- adjacency packing ----------------
__global__ void pack_adj_k(const int* __restrict__ adj, unsigned* __restrict__ bits) {
    int gid = blockIdx.x * blockDim.x + threadIdx.x;
    unsigned pred = adj[gid] > 0 ? 1u : 0u;
    unsigned word = __ballot_sync(0xffffffffu, pred);
    if ((threadIdx.x & 31) == 0) bits[gid >> 5] = word;
}

// ---------------- 3xTF32 MMA GEMM: C = A@B (+bias), fp32-accurate ----------------
__global__ __launch_bounds__(256, 2)
void gemm3t_k(const float* __restrict__ A, const float* __restrict__ B,
              const float* __restrict__ bias, float* __restrict__ C,
              int M, int N, int K) {
    constexpr int BM = 128, BN = 64, BK = 32;
    constexpr int AS = BK + 4;
    constexpr int BS = BN + 4;
    __shared__ unsigned Ah[BM * AS], Al[BM * AS];
    __shared__ unsigned Bh[BK * BS], Bl[BK * BS];

    int t = threadIdx.x;
    int wid = t >> 5, lane = t & 31;
    int gid = lane >> 2, tid4 = lane & 3;
    int m0 = blockIdx.y * BM, n0 = blockIdx.x * BN;
    int wm = (wid & 3) * 32, wn = (wid >> 2) * 32;

    float acc[2][4][4];
#pragma unroll
    for (int mf = 0; mf < 2; mf++)
#pragma unroll
        for (int nf = 0; nf < 4; nf++)
#pragma unroll
            for (int c = 0; c < 4; c++) acc[mf][nf][c] = 0.f;

    for (int k0 = 0; k0 < K; k0 += BK) {
#pragma unroll
        for (int i = 0; i < (BM * BK) / 256; i++) {
            int e = t + i * 256;
            int m = e / BK, k = e % BK;
            unsigned h, l;
            split_tf32(A[(size_t)(m0 + m) * K + k0 + k], h, l);
            Ah[m * AS + k] = h; Al[m * AS + k] = l;
        }
#pragma unroll
        for (int i = 0; i < (BK * BN) / 256; i++) {
            int e = t + i * 256;
            int k = e / BN, n = e % BN;
            unsigned h, l;
            split_tf32(B[(size_t)(k0 + k) * N + n0 + n], h, l);
            Bh[k * BS + n] = h; Bl[k * BS + n] = l;
        }
        __syncthreads();

#pragma unroll
        for (int k8 = 0; k8 < BK / 8; k8++) {
            unsigned ah[2][4], al[2][4];
#pragma unroll
            for (int mf = 0; mf < 2; mf++) {
                int r0 = wm + mf * 16 + gid;
                ah[mf][0] = Ah[r0 * AS + k8 * 8 + tid4];
                ah[mf][1] = Ah[(r0 + 8) * AS + k8 * 8 + tid4];
                ah[mf][2] = Ah[r0 * AS + k8 * 8 + tid4 + 4];
                ah[mf][3] = Ah[(r0 + 8) * AS + k8 * 8 + tid4 + 4];
                al[mf][0] = Al[r0 * AS + k8 * 8 + tid4];
                al[mf][1] = Al[(r0 + 8) * AS + k8 * 8 + tid4];
                al[mf][2] = Al[r0 * AS + k8 * 8 + tid4 + 4];
                al[mf][3] = Al[(r0 + 8) * AS + k8 * 8 + tid4 + 4];
            }
#pragma unroll
            for (int nf = 0; nf < 4; nf++) {
                int cb = wn + nf * 8 + gid;
                unsigned bh0 = Bh[(k8 * 8 + tid4) * BS + cb];
                unsigned bh1 = Bh[(k8 * 8 + tid4 + 4) * BS + cb];
                unsigned bl0 = Bl[(k8 * 8 + tid4) * BS + cb];
                unsigned bl1 = Bl[(k8 * 8 + tid4 + 4) * BS + cb];
#pragma unroll
                for (int mf = 0; mf < 2; mf++) {
                    MMA_TF32(acc[mf][nf], ah[mf][0], ah[mf][1], ah[mf][2], ah[mf][3], bh0, bh1);
                    MMA_TF32(acc[mf][nf], ah[mf][0], ah[mf][1], ah[mf][2], ah[mf][3], bl0, bl1);
                    MMA_TF32(acc[mf][nf], al[mf][0], al[mf][1], al[mf][2], al[mf][3], bh0, bh1);
                }
            }
        }
        __syncthreads();
    }

#pragma unroll
    for (int mf = 0; mf < 2; mf++) {
        int r0 = m0 + wm + mf * 16 + gid;
#pragma unroll
        for (int nf = 0; nf < 4; nf++) {
            int col = n0 + wn + nf * 8 + tid4 * 2;
            float b0 = bias ? bias[col] : 0.f;
            float b1 = bias ? bias[col + 1] : 0.f;
            float2 v0 = make_float2(acc[mf][nf][0] + b0, acc[mf][nf][1] + b1);
            float2 v1 = make_float2(acc[mf][nf][2] + b0, acc[mf][nf][3] + b1);
            *reinterpret_cast<float2*>(&C[(size_t)r0 * N + col]) = v0;
            *reinterpret_cast<float2*>(&C[(size_t)(r0 + 8) * N + col]) = v1;
        }
    }
}

// ---------------- generic fp32 tiled GEMM (small cases) ----------------
template<int BM, int BN, int BK, int TM, int TN>
__global__ void gemm_k(const float* __restrict__ A, const float* __restrict__ B,
                       const float* __restrict__ bias, float* __restrict__ C,
                       int M, int N, int K) {
    __shared__ float As[BK][BM];
    __shared__ float Bs[BK][BN];
    constexpr int TX = BN / TN;
    int tid = threadIdx.x;
    int tx = tid % TX, ty = tid / TX;
    int m0 = blockIdx.y * BM, n0 = blockIdx.x * BN;
    float acc[TM][TN];
#pragma unroll
    for (int i = 0; i < TM; i++)
#pragma unroll
        for (int j = 0; j < TN; j++) acc[i][j] = 0.f;

    for (int k0 = 0; k0 < K; k0 += BK) {
#pragma unroll
        for (int idx = tid; idx < BM * BK; idx += 256) {
            int m = idx / BK, k = idx % BK;
            As[k][m] = A[(m0 + m) * K + k0 + k];
        }
#pragma unroll
        for (int idx = tid; idx < BK * BN; idx += 256) {
            int k = idx / BN, n = idx % BN;
            Bs[k][n] = B[(k0 + k) * N + n0 + n];
        }
        __syncthreads();
#pragma unroll
        for (int k = 0; k < BK; k++) {
            float ra[TM], rb[TN];
#pragma unroll
            for (int i = 0; i < TM; i++) ra[i] = As[k][ty * TM + i];
#pragma unroll
            for (int j = 0; j < TN; j++) rb[j] = Bs[k][tx * TN + j];
#pragma unroll
            for (int i = 0; i < TM; i++)
#pragma unroll
                for (int j = 0; j < TN; j++) acc[i][j] = fmaf(ra[i], rb[j], acc[i][j]);
        }
        __syncthreads();
    }
#pragma unroll
    for (int i = 0; i < TM; i++)
#pragma unroll
        for (int j = 0; j < TN; j++) {
            float v = acc[i][j];
            if (bias) v += bias[n0 + tx * TN + j];
            C[(m0 + ty * TM + i) * N + n0 + tx * TN + j] = v;
        }
}

// ---------------- per-node logits -> factorized exponentials ----------------
template<int F>
__global__ void esed_k(const float* __restrict__ h, const float* __restrict__ asv,
                       const float* __restrict__ adv, float2* __restrict__ rowc,
                       float2* __restrict__ evq) {
    int n = blockIdx.x;
    int t = threadIdx.x;  // 128
    __shared__ float rs[128], rd[128];
    for (int hd = 0; hd < HH; hd++) {
        float vs = 0.f, vd = 0.f;
        for (int f = t; f < F; f += 128) {
            float hv = h[n * (HH * F) + hd * F + f];
            vs = fmaf(hv, asv[hd * F + f], vs);
            vd = fmaf(hv, adv[hd * F + f], vd);
        }
        rs[t] = vs; rd[t] = vd;
        __syncthreads();
#pragma unroll
        for (int s = 64; s > 0; s >>= 1) {
            if (t < s) { rs[t] += rs[t + s]; rd[t] += rd[t + s]; }
            __syncthreads();
        }
        if (t == 0) {
            float es0 = rs[0], ed0 = rd[0];
            rowc[hd * NN + n] = make_float2(expf(es0), expf(0.2f * es0));
            evq [hd * NN + n] = make_float2(expf(ed0), expf(0.2f * ed0));
        }
        __syncthreads();
    }
}

// ---------------- fused masked-softmax GAT aggregation (tf32 mma) ----------------
// 4 warps x 32 rows (MFRAG=2) = IT=128 rows, 128 threads/block.
// Each warp owns all FE cols -> B fragments loaded once per 2 m-frags.
// JSPLIT==1: blockIdx.z splits F; JSPLIT>1: blockIdx.z splits j-range
// (unscaled numerator -> pnum, partial denominator -> pden).
template<int F, int FE, int JSPLIT>
__global__ __launch_bounds__(128, 4)
void attn_mma_k(const float* __restrict__ h, const float2* __restrict__ rowc,
                const float2* __restrict__ evq, const unsigned* __restrict__ bits,
                float* __restrict__ out, float* __restrict__ pnum,
                float* __restrict__ pden) {
    constexpr int IT = 128;
    constexpr int JT = 64;
    constexpr int HS = FE + 8;
    constexpr int NFRAG = FE / 8;
    constexpr int HF = HH * F;
    constexpr int NV = FE / 4;
    constexpr int JSPAN = NN / JSPLIT;
    constexpr int NT = JSPAN / JT;

    __shared__ float  hs[2][JT * HS];
    __shared__ float2 evq_s[2][JT];
    __shared__ uint2  bits_s[2][IT];
    __shared__ float2 rowc_s[IT];
    __shared__ float  dens[IT];

    int t = threadIdx.x;           // 0..127
    int wid = t >> 5, lane = t & 31;
    int gid = lane >> 2, tid4 = lane & 3;
    int head = blockIdx.y;
    int i0 = blockIdx.x * IT;
    int zz = blockIdx.z;
    int fofs = (JSPLIT == 1) ? zz * FE : 0;
    int jbeg = (JSPLIT == 1) ? 0 : zz * JSPAN;

    int rbase = wid * 32 + gid;    // rows rbase + q*8, q=0..3 (mfrag q/2)

    rowc_s[t] = rowc[head * NN + i0 + t];

    const float* hbase = h + head * F + fofs;
    const unsigned* bbase = bits + (size_t)i0 * (NN / 32);

    auto load_tile = [&](int st, int j0) {
#pragma unroll
        for (int idx = t; idx < JT * NV; idx += 128) {
            int jj = idx / NV, fv = idx % NV;
            CP_ASYNC16(smem_u32(&hs[st][jj * HS + fv * 4]),
                       hbase + (size_t)(j0 + jj) * HF + fv * 4);
        }
        if (t < JT) CP_ASYNC8(smem_u32(&evq_s[st][t]), evq + head * NN + j0 + t);
        CP_ASYNC8(smem_u32(&bits_s[st][t]), bbase + (size_t)t * (NN / 32) + (j0 >> 5));
        CP_COMMIT();
    };

    float acc[2][NFRAG][4];
#pragma unroll
    for (int mf = 0; mf < 2; mf++)
#pragma unroll
        for (int nf = 0; nf < NFRAG; nf++)
#pragma unroll
            for (int c = 0; c < 4; c++) acc[mf][nf][c] = 0.f;
    float dacc[4] = {0.f, 0.f, 0.f, 0.f};

    load_tile(0, jbeg);

    for (int tt = 0; tt < NT; tt++) {
        int st = tt & 1;
        if (tt + 1 < NT) { load_tile(st ^ 1, jbeg + (tt + 1) * JT); CP_WAIT1(); }
        else             { CP_WAIT0(); }
        __syncthreads();

        float2 rc[4];
        uint2  bw[4];
#pragma unroll
        for (int q = 0; q < 4; q++) {
            rc[q] = rowc_s[rbase + q * 8];
            bw[q] = bits_s[st][rbase + q * 8];
        }
        const unsigned* hsu = reinterpret_cast<const unsigned*>(hs[st]);

#pragma unroll
        for (int k = 0; k < JT / 8; k++) {
            int c0 = k * 8 + tid4, c1 = c0 + 4;
            float2 e0 = evq_s[st][c0], e1 = evq_s[st][c1];
            int s0 = c0 & 31, s1 = c1 & 31;

            float w0[4], w1[4];
#pragma unroll
            for (int q = 0; q < 4; q++) {
                unsigned wq = (k < 4) ? bw[q].x : bw[q].y;
                float a = fmaxf(rc[q].x * e0.x, rc[q].y * e0.y);
                if (!((wq >> s0) & 1u)) a = 0.f;
                float b = fmaxf(rc[q].x * e1.x, rc[q].y * e1.y);
                if (!((wq >> s1) & 1u)) b = 0.f;
                w0[q] = a; w1[q] = b;
                dacc[q] += a + b;
            }

            unsigned am0[4] = {__float_as_uint(w0[0]), __float_as_uint(w0[1]),
                               __float_as_uint(w1[0]), __float_as_uint(w1[1])};
            unsigned am1[4] = {__float_as_uint(w0[2]), __float_as_uint(w0[3]),
                               __float_as_uint(w1[2]), __float_as_uint(w1[3])};

#pragma unroll
            for (int nf = 0; nf < NFRAG; nf++) {
                unsigned b0 = hsu[c0 * HS + nf * 8 + gid];
                unsigned b1 = hsu[c1 * HS + nf * 8 + gid];
                MMA_TF32(acc[0][nf], am0[0], am0[1], am0[2], am0[3], b0, b1);
                MMA_TF32(acc[1][nf], am1[0], am1[1], am1[2], am1[3], b0, b1);
            }
        }
        __syncthreads();
    }

    // quad-lane reduce of denominators
#pragma unroll
    for (int q = 0; q < 4; q++) {
        dacc[q] += __shfl_xor_sync(0xffffffffu, dacc[q], 1);
        dacc[q] += __shfl_xor_sync(0xffffffffu, dacc[q], 2);
    }
    if (tid4 == 0) {
#pragma unroll
        for (int q = 0; q < 4; q++) dens[rbase + q * 8] = dacc[q];
    }
    __syncthreads();

    if (JSPLIT == 1) {
        float iv[4];
#pragma unroll
        for (int q = 0; q < 4; q++) iv[q] = 1.f / dens[rbase + q * 8];
#pragma unroll
        for (int mf = 0; mf < 2; mf++)
#pragma unroll
            for (int nf = 0; nf < NFRAG; nf++) {
                int col = head * F + fofs + nf * 8 + tid4 * 2;
                int ra = i0 + rbase + mf * 16;
                float2 v0 = make_float2(acc[mf][nf][0] * iv[mf * 2],
                                        acc[mf][nf][1] * iv[mf * 2]);
                float2 v1 = make_float2(acc[mf][nf][2] * iv[mf * 2 + 1],
                                        acc[mf][nf][3] * iv[mf * 2 + 1]);
                *reinterpret_cast<float2*>(&out[(size_t)ra * HF + col]) = v0;
                *reinterpret_cast<float2*>(&out[(size_t)(ra + 8) * HF + col]) = v1;
            }
    } else {
        if (tid4 == 0) {
#pragma unroll
            for (int q = 0; q < 4; q++)
                pden[((size_t)zz * HH + head) * NN + i0 + rbase + q * 8] = dacc[q];
        }
        float* pb = pnum + (size_t)zz * NN * HF;
#pragma unroll
        for (int mf = 0; mf < 2; mf++)
#pragma unroll
            for (int nf = 0; nf < NFRAG; nf++) {
                int col = head * F + nf * 8 + tid4 * 2;
                int ra = i0 + rbase + mf * 16;
                float2 v0 = make_float2(acc[mf][nf][0], acc[mf][nf][1]);
                float2 v1 = make_float2(acc[mf][nf][2], acc[mf][nf][3]);
                *reinterpret_cast<float2*>(&pb[(size_t)ra * HF + col]) = v0;
                *reinterpret_cast<float2*>(&pb[(size_t)(ra + 8) * HF + col]) = v1;
            }
    }
}

// combine attn2 j-split partials: out = sum(p)/sum(d) over 4 splits
__global__ void combine4_k(const float* __restrict__ p, const float* __restrict__ dp,
                           float* __restrict__ out) {
    int n = blockIdx.x;
    int t = threadIdx.x;      // 128 = HF for layer 2
    int head = t >> 5;
    float d = 0.f, v = 0.f;
#pragma unroll
    for (int z = 0; z < 4; z++) {
        d += dp[((size_t)z * HH + head) * NN + n];
        v += p[(size_t)z * NN * 128 + (size_t)n * 128 + t];
    }
    out[(size_t)n * 128 + t] = v / d;
}

// ---------------- batchnorm stats ----------------
template<int C>
__global__ void bnstats_k(const float* __restrict__ y, float* __restrict__ stats) {
    int c = blockIdx.x;
    int t = threadIdx.x;  // 256
    float s = 0.f, q = 0.f;
    for (int r = t; r < NN; r += 256) {
        float v = y[r * C + c];
        s += v; q = fmaf(v, v, q);
    }
    __shared__ float ss[256], qq[256];
    ss[t] = s; qq[t] = q;
    __syncthreads();
#pragma unroll
    for (int o = 128; o > 0; o >>= 1) {
        if (t < o) { ss[t] += ss[t + o]; qq[t] += qq[t + o]; }
        __syncthreads();
    }
    if (t == 0) {
        float mean = ss[0] / (float)NN;
        float var  = qq[0] / (float)NN - mean * mean;
        stats[c]       = mean;
        stats[128 + c] = rsqrtf(var + 1e-5f);
    }
}

// ---------------- normalize + affine + ELU ----------------
template<int C>
__global__ void bnelu_k(const float* __restrict__ y, const float* __restrict__ stats,
                        const float* __restrict__ g, const float* __restrict__ b,
                        float* __restrict__ out) {
    int idx = blockIdx.x * blockDim.x + threadIdx.x;
    if (idx >= NN * C) return;
    int c = idx % C;
    float v = (y[idx] - stats[c]) * stats[128 + c];
    v = fmaf(v, g[c], b[c]);
    out[idx] = v > 0.f ? v : expm1f(v);
}

// ---------------- launch ----------------
extern "C" void kernel_launch(void* const* d_in, const int* in_sizes, int n_in,
                              void* d_out, int out_size) {
    const float* x   = (const float*)d_in[0];
    const int*   adj = (const int*)d_in[1];
    const float* W1  = (const float*)d_in[2];
    const float* a1s = (const float*)d_in[3];
    const float* a1d = (const float*)d_in[4];
    const float* lw1 = (const float*)d_in[5];
    const float* lb1 = (const float*)d_in[6];
    const float* g1  = (const float*)d_in[7];
    const float* be1 = (const float*)d_in[8];
    const float* W2  = (const float*)d_in[9];
    const float* a2s = (const float*)d_in[10];
    const float* a2d = (const float*)d_in[11];
    const float* lw2 = (const float*)d_in[12];
    const float* lb2 = (const float*)d_in[13];
    const float* g2  = (const float*)d_in[14];
    const float* be2 = (const float*)d_in[15];
    float* out = (float*)d_out;

    float *h1, *x1, *y1, *x2, *h2, *x3, *y2, *stats, *part, *dpart;
    float2 *rowc1, *evq1, *rowc2, *evq2;
    unsigned* bitsp;
    cudaGetSymbolAddress((void**)&h1,  g_h1);
    cudaGetSymbolAddress((void**)&x1,  g_x1);
    cudaGetSymbolAddress((void**)&y1,  g_y1);
    cudaGetSymbolAddress((void**)&x2,  g_x2);
    cudaGetSymbolAddress((void**)&h2,  g_h2);
    cudaGetSymbolAddress((void**)&x3,  g_x3);
    cudaGetSymbolAddress((void**)&y2,  g_y2);
    cudaGetSymbolAddress((void**)&rowc1, g_rowc1);
    cudaGetSymbolAddress((void**)&evq1,  g_evq1);
    cudaGetSymbolAddress((void**)&rowc2, g_rowc2);
    cudaGetSymbolAddress((void**)&evq2,  g_evq2);
    cudaGetSymbolAddress((void**)&stats, g_stats);
    cudaGetSymbolAddress((void**)&part,  g_part);
    cudaGetSymbolAddress((void**)&dpart, g_dpart);
    cudaGetSymbolAddress((void**)&bitsp, g_adjbits);

    // pack adjacency to bits
    pack_adj_k<<<(NN * NN) / 256, 256>>>(adj, bitsp);

    // ---- layer 1 GAT ----
    gemm3t_k<<<dim3(512 / 64, NN / 128), 256>>>(x, W1, nullptr, h1, NN, 512, 512);
    esed_k<128><<<NN, 128>>>(h1, a1s, a1d, rowc1, evq1);
    // F=128, FE=64 (z splits F) -> grid 32x4x2 = 256 blocks of 128 thr (one wave)
    attn_mma_k<128, 64, 1><<<dim3(NN / 128, HH, 2), 128>>>(h1, rowc1, evq1, bitsp, x1, nullptr, nullptr);

    // ---- MLP 1 + BN + ELU ----
    gemm3t_k<<<dim3(1, NN / 128), 256>>>(x1, lw1, lb1, y1, NN, 64, 512);
    bnstats_k<64><<<64, 256>>>(y1, stats);
    bnelu_k<64><<<(NN * 64) / 256, 256>>>(y1, stats, g1, be1, x2);

    // ---- layer 2 GAT ----
    gemm_k<128, 64, 16, 8, 4><<<dim3(2, NN / 128), 256>>>(x2, W2, nullptr, h2, NN, 128, 64);
    esed_k<32><<<NN, 128>>>(h2, a2s, a2d, rowc2, evq2);
    // F=FE=32, j-split x4 -> grid 32x4x4 = 512 blocks of 128 thr (one wave)
    attn_mma_k<32, 32, 4><<<dim3(NN / 128, HH, 4), 128>>>(h2, rowc2, evq2, bitsp, nullptr, part, dpart);
    combine4_k<<<NN, 128>>>(part, dpart, x3);

    // ---- MLP 2 + BN + ELU ----
    gemm_k<64, 16, 16, 4, 1><<<dim3(1, NN / 64), 256>>>(x3, lw2, lb2, y2, NN, 16, 128);
    bnstats_k<16><<<16, 256>>>(y2, stats);
    bnelu_k<16><<<(NN * 16) / 256, 256>>>(y2, stats, g2, be2, out);
}

// round 12
// speedup vs baseline: 1.0301x; 1.0301x over previous
#include <cuda_runtime.h>
#include <cuda_bf16.h>
#include <cstdint>

#define NN 4096
#define HH 4

// ---------------- scratch ----------------
__device__ float  g_h1 [NN * 512];
__device__ float  g_x1 [NN * 512];
__device__ float  g_y1 [NN * 64];
__device__ float  g_x2 [NN * 64];
__device__ float  g_h2 [NN * 128];
__device__ float  g_x3 [NN * 128];
__device__ float  g_y2 [NN * 16];
__device__ float2 g_rowc1[HH * NN];   // {e^es, e^{0.2es}}
__device__ float2 g_evq1 [HH * NN];   // {e^ed, e^{0.2ed}}
__device__ float2 g_rowc2[HH * NN];
__device__ float2 g_evq2 [HH * NN];
__device__ unsigned g_adjbits[NN * (NN / 32)];
__device__ float  g_stats[256];
__device__ float  g_part [2 * NN * 512];   // attn partial numerators (max: attn1 2 splits x HF=512)
__device__ float  g_dpart[4 * HH * NN];    // partial denominators
__device__ unsigned g_spAh[NN * 512], g_spAl[NN * 512];   // pre-split A (tf32 hi/lo)
__device__ unsigned g_spBh[512 * 512], g_spBl[512 * 512]; // pre-split B

// ---------------- helpers ----------------
__device__ __forceinline__ unsigned smem_u32(const void* p) {
    return (unsigned)__cvta_generic_to_shared(p);
}
#define CP_ASYNC16(dst, src) \
    asm volatile("cp.async.cg.shared.global [%0], [%1], 16;" :: "r"(dst), "l"(src))
#define CP_ASYNC8(dst, src) \
    asm volatile("cp.async.ca.shared.global [%0], [%1], 8;" :: "r"(dst), "l"(src))
#define CP_COMMIT() asm volatile("cp.async.commit_group;")
#define CP_WAIT1()  asm volatile("cp.async.wait_group 1;")
#define CP_WAIT0()  asm volatile("cp.async.wait_group 0;")

#define MMA_TF32(acc, a0, a1, a2, a3, b0, b1)                                   \
    asm volatile(                                                               \
        "mma.sync.aligned.m16n8k8.row.col.f32.tf32.tf32.f32 "                   \
        "{%0,%1,%2,%3}, {%4,%5,%6,%7}, {%8,%9}, {%0,%1,%2,%3};"                 \
        : "+f"(acc[0]), "+f"(acc[1]), "+f"(acc[2]), "+f"(acc[3])                \
        : "r"(a0), "r"(a1), "r"(a2), "r"(a3), "r"(b0), "r"(b1))

__device__ __forceinline__ void split_tf32(float v, unsigned& h, unsigned& l) {
    unsigned hv;
    asm("cvt.rna.tf32.f32 %0, %1;" : "=r"(hv) : "f"(v));
    float lo = v - __uint_as_float(hv);
    unsigned lv;
    asm("cvt.rna.tf32.f32 %0, %1;" : "=r"(lv) : "f"(lo));
    h = hv; l = lv;
}

// ---------------- adjacency packing ----------------
__global__ void pack_adj_k(const int* __restrict__ adj, unsigned* __restrict__ bits) {
    int gid = blockIdx.x * blockDim.x + threadIdx.x;
    unsigned pred = adj[gid] > 0 ? 1u : 0u;
    unsigned word = __ballot_sync(0xffffffffu, pred);
    if ((threadIdx.x & 31) == 0) bits[gid >> 5] = word;
}

// ---------------- tf32 hi/lo pre-split (elementwise) ----------------
__global__ void presplit_k(const float* __restrict__ a, unsigned* __restrict__ hi,
                           unsigned* __restrict__ lo, int n) {
    int i = blockIdx.x * blockDim.x + threadIdx.x;
    if (i >= n) return;
    unsigned h, l;
    split_tf32(a[i], h, l);
    hi[i] = h; lo[i] = l;
}

// ---------------- 3xTF32 MMA GEMM on pre-split inputs ----------------
// C = A@B (+bias); A,B given as tf32 hi/lo planes. BM=128,BN=64,BK=32; 8 warps.
__global__ __launch_bounds__(256, 2)
void gemm3t_pre_k(const unsigned* __restrict__ Agh, const unsigned* __restrict__ Agl,
                  const unsigned* __restrict__ Bgh, const unsigned* __restrict__ Bgl,
                  const float* __restrict__ bias, float* __restrict__ C,
                  int M, int N, int K) {
    constexpr int BM = 128, BN = 64, BK = 32;
    constexpr int AS = BK + 4;
    constexpr int BS = BN + 4;
    __shared__ unsigned Ah[BM * AS], Al[BM * AS];
    __shared__ unsigned Bh[BK * BS], Bl[BK * BS];

    int t = threadIdx.x;
    int wid = t >> 5, lane = t & 31;
    int gid = lane >> 2, tid4 = lane & 3;
    int m0 = blockIdx.y * BM, n0 = blockIdx.x * BN;
    int wm = (wid & 3) * 32, wn = (wid >> 2) * 32;

    float acc[2][4][4];
#pragma unroll
    for (int mf = 0; mf < 2; mf++)
#pragma unroll
        for (int nf = 0; nf < 4; nf++)
#pragma unroll
            for (int c = 0; c < 4; c++) acc[mf][nf][c] = 0.f;

    for (int k0 = 0; k0 < K; k0 += BK) {
        // A tiles: BM x BK, 16B chunks (BK/4 = 8 per row)
#pragma unroll
        for (int i = 0; i < (BM * BK) / (256 * 4); i++) {
            int e = (t + i * 256) * 4;
            int m = e / BK, k = e % BK;
            CP_ASYNC16(smem_u32(&Ah[m * AS + k]), Agh + (size_t)(m0 + m) * K + k0 + k);
            CP_ASYNC16(smem_u32(&Al[m * AS + k]), Agl + (size_t)(m0 + m) * K + k0 + k);
        }
        // B tiles: BK x BN
#pragma unroll
        for (int i = 0; i < (BK * BN) / (256 * 4); i++) {
            int e = (t + i * 256) * 4;
            int k = e / BN, n = e % BN;
            CP_ASYNC16(smem_u32(&Bh[k * BS + n]), Bgh + (size_t)(k0 + k) * N + n0 + n);
            CP_ASYNC16(smem_u32(&Bl[k * BS + n]), Bgl + (size_t)(k0 + k) * N + n0 + n);
        }
        CP_COMMIT();
        CP_WAIT0();
        __syncthreads();

#pragma unroll
        for (int k8 = 0; k8 < BK / 8; k8++) {
            unsigned ah[2][4], al[2][4];
#pragma unroll
            for (int mf = 0; mf < 2; mf++) {
                int r0 = wm + mf * 16 + gid;
                ah[mf][0] = Ah[r0 * AS + k8 * 8 + tid4];
                ah[mf][1] = Ah[(r0 + 8) * AS + k8 * 8 + tid4];
                ah[mf][2] = Ah[r0 * AS + k8 * 8 + tid4 + 4];
                ah[mf][3] = Ah[(r0 + 8) * AS + k8 * 8 + tid4 + 4];
                al[mf][0] = Al[r0 * AS + k8 * 8 + tid4];
                al[mf][1] = Al[(r0 + 8) * AS + k8 * 8 + tid4];
                al[mf][2] = Al[r0 * AS + k8 * 8 + tid4 + 4];
                al[mf][3] = Al[(r0 + 8) * AS + k8 * 8 + tid4 + 4];
            }
#pragma unroll
            for (int nf = 0; nf < 4; nf++) {
                int cb = wn + nf * 8 + gid;
                unsigned bh0 = Bh[(k8 * 8 + tid4) * BS + cb];
                unsigned bh1 = Bh[(k8 * 8 + tid4 + 4) * BS + cb];
                unsigned bl0 = Bl[(k8 * 8 + tid4) * BS + cb];
                unsigned bl1 = Bl[(k8 * 8 + tid4 + 4) * BS + cb];
#pragma unroll
                for (int mf = 0; mf < 2; mf++) {
                    MMA_TF32(acc[mf][nf], ah[mf][0], ah[mf][1], ah[mf][2], ah[mf][3], bh0, bh1);
                    MMA_TF32(acc[mf][nf], ah[mf][0], ah[mf][1], ah[mf][2], ah[mf][3], bl0, bl1);
                    MMA_TF32(acc[mf][nf], al[mf][0], al[mf][1], al[mf][2], al[mf][3], bh0, bh1);
                }
            }
        }
        __syncthreads();
    }

#pragma unroll
    for (int mf = 0; mf < 2; mf++) {
        int r0 = m0 + wm + mf * 16 + gid;
#pragma unroll
        for (int nf = 0; nf < 4; nf++) {
            int col = n0 + wn + nf * 8 + tid4 * 2;
            float b0 = bias ? bias[col] : 0.f;
            float b1 = bias ? bias[col + 1] : 0.f;
            float2 v0 = make_float2(acc[mf][nf][0] + b0, acc[mf][nf][1] + b1);
            float2 v1 = make_float2(acc[mf][nf][2] + b0, acc[mf][nf][3] + b1);
            *reinterpret_cast<float2*>(&C[(size_t)r0 * N + col]) = v0;
            *reinterpret_cast<float2*>(&C[(size_t)(r0 + 8) * N + col]) = v1;
        }
    }
}

// ---------------- generic fp32 tiled GEMM (small cases) ----------------
template<int BM, int BN, int BK, int TM, int TN>
__global__ void gemm_k(const float* __restrict__ A, const float* __restrict__ B,
                       const float* __restrict__ bias, float* __restrict__ C,
                       int M, int N, int K) {
    __shared__ float As[BK][BM];
    __shared__ float Bs[BK][BN];
    constexpr int TX = BN / TN;
    int tid = threadIdx.x;
    int tx = tid % TX, ty = tid / TX;
    int m0 = blockIdx.y * BM, n0 = blockIdx.x * BN;
    float acc[TM][TN];
#pragma unroll
    for (int i = 0; i < TM; i++)
#pragma unroll
        for (int j = 0; j < TN; j++) acc[i][j] = 0.f;

    for (int k0 = 0; k0 < K; k0 += BK) {
#pragma unroll
        for (int idx = tid; idx < BM * BK; idx += 256) {
            int m = idx / BK, k = idx % BK;
            As[k][m] = A[(m0 + m) * K + k0 + k];
        }
#pragma unroll
        for (int idx = tid; idx < BK * BN; idx += 256) {
            int k = idx / BN, n = idx % BN;
            Bs[k][n] = B[(k0 + k) * N + n0 + n];
        }
        __syncthreads();
#pragma unroll
        for (int k = 0; k < BK; k++) {
            float ra[TM], rb[TN];
#pragma unroll
            for (int i = 0; i < TM; i++) ra[i] = As[k][ty * TM + i];
#pragma unroll
            for (int j = 0; j < TN; j++) rb[j] = Bs[k][tx * TN + j];
#pragma unroll
            for (int i = 0; i < TM; i++)
#pragma unroll
                for (int j = 0; j < TN; j++) acc[i][j] = fmaf(ra[i], rb[j], acc[i][j]);
        }
        __syncthreads();
    }
#pragma unroll
    for (int i = 0; i < TM; i++)
#pragma unroll
        for (int j = 0; j < TN; j++) {
            float v = acc[i][j];
            if (bias) v += bias[n0 + tx * TN + j];
            C[(m0 + ty * TM + i) * N + n0 + tx * TN + j] = v;
        }
}

// ---------------- per-node logits -> factorized exponentials ----------------
template<int F>
__global__ void esed_k(const float* __restrict__ h, const float* __restrict__ asv,
                       const float* __restrict__ adv, float2* __restrict__ rowc,
                       float2* __restrict__ evq) {
    int n = blockIdx.x;
    int t = threadIdx.x;  // 128
    __shared__ float rs[128], rd[128];
    for (int hd = 0; hd < HH; hd++) {
        float vs = 0.f, vd = 0.f;
        for (int f = t; f < F; f += 128) {
            float hv = h[n * (HH * F) + hd * F + f];
            vs = fmaf(hv, asv[hd * F + f], vs);
            vd = fmaf(hv, adv[hd * F + f], vd);
        }
        rs[t] = vs; rd[t] = vd;
        __syncthreads();
#pragma unroll
        for (int s = 64; s > 0; s >>= 1) {
            if (t < s) { rs[t] += rs[t + s]; rd[t] += rd[t + s]; }
            __syncthreads();
        }
        if (t == 0) {
            float es0 = rs[0], ed0 = rd[0];
            rowc[hd * NN + n] = make_float2(expf(es0), expf(0.2f * es0));
            evq [hd * NN + n] = make_float2(expf(ed0), expf(0.2f * ed0));
        }
        __syncthreads();
    }
}

// ---------------- fused masked-softmax GAT aggregation (tf32 mma) ----------------
// 4 warps x 32 rows (MFRAG=2) = IT=128 rows, 128 threads/block.
// blockIdx.z encodes (fs, js): fs splits F into FE chunks, js splits the
// j-range. If JSPLIT==1 output is scaled+direct; else unscaled numerator ->
// pnum[js] and denominator -> pden[js] (written by fs==0 only), combined later.
template<int F, int FE, int FSPLIT, int JSPLIT>
__global__ __launch_bounds__(128, 4)
void attn_mma_k(const float* __restrict__ h, const float2* __restrict__ rowc,
                const float2* __restrict__ evq, const unsigned* __restrict__ bits,
                float* __restrict__ out, float* __restrict__ pnum,
                float* __restrict__ pden) {
    constexpr int IT = 128;
    constexpr int JT = 64;
    constexpr int HS = FE + 8;
    constexpr int NFRAG = FE / 8;
    constexpr int HF = HH * F;
    constexpr int NV = FE / 4;
    constexpr int JSPAN = NN / JSPLIT;
    constexpr int NT = JSPAN / JT;

    __shared__ float  hs[2][JT * HS];
    __shared__ float2 evq_s[2][JT];
    __shared__ uint2  bits_s[2][IT];
    __shared__ float2 rowc_s[IT];
    __shared__ float  dens[IT];

    int t = threadIdx.x;           // 0..127
    int wid = t >> 5, lane = t & 31;
    int gid = lane >> 2, tid4 = lane & 3;
    int head = blockIdx.y;
    int i0 = blockIdx.x * IT;
    int zz = blockIdx.z;
    int fs = zz % FSPLIT, js = zz / FSPLIT;
    int fofs = fs * FE;
    int jbeg = js * JSPAN;

    int rbase = wid * 32 + gid;    // rows rbase + q*8, q=0..3 (mfrag q/2)

    rowc_s[t] = rowc[head * NN + i0 + t];

    const float* hbase = h + head * F + fofs;
    const unsigned* bbase = bits + (size_t)i0 * (NN / 32);

    auto load_tile = [&](int st, int j0) {
#pragma unroll
        for (int idx = t; idx < JT * NV; idx += 128) {
            int jj = idx / NV, fv = idx % NV;
            CP_ASYNC16(smem_u32(&hs[st][jj * HS + fv * 4]),
                       hbase + (size_t)(j0 + jj) * HF + fv * 4);
        }
        if (t < JT) CP_ASYNC8(smem_u32(&evq_s[st][t]), evq + head * NN + j0 + t);
        CP_ASYNC8(smem_u32(&bits_s[st][t]), bbase + (size_t)t * (NN / 32) + (j0 >> 5));
        CP_COMMIT();
    };

    float acc[2][NFRAG][4];
#pragma unroll
    for (int mf = 0; mf < 2; mf++)
#pragma unroll
        for (int nf = 0; nf < NFRAG; nf++)
#pragma unroll
            for (int c = 0; c < 4; c++) acc[mf][nf][c] = 0.f;
    float dacc[4] = {0.f, 0.f, 0.f, 0.f};

    load_tile(0, jbeg);

    for (int tt = 0; tt < NT; tt++) {
        int st = tt & 1;
        if (tt + 1 < NT) { load_tile(st ^ 1, jbeg + (tt + 1) * JT); CP_WAIT1(); }
        else             { CP_WAIT0(); }
        __syncthreads();

        float2 rc[4];
        uint2  bw[4];
#pragma unroll
        for (int q = 0; q < 4; q++) {
            rc[q] = rowc_s[rbase + q * 8];
            bw[q] = bits_s[st][rbase + q * 8];
        }
        const unsigned* hsu = reinterpret_cast<const unsigned*>(hs[st]);

#pragma unroll
        for (int k = 0; k < JT / 8; k++) {
            int c0 = k * 8 + tid4, c1 = c0 + 4;
            float2 e0 = evq_s[st][c0], e1 = evq_s[st][c1];
            int s0 = c0 & 31, s1 = c1 & 31;

            float w0[4], w1[4];
#pragma unroll
            for (int q = 0; q < 4; q++) {
                unsigned wq = (k < 4) ? bw[q].x : bw[q].y;
                float a = fmaxf(rc[q].x * e0.x, rc[q].y * e0.y);
                if (!((wq >> s0) & 1u)) a = 0.f;
                float b = fmaxf(rc[q].x * e1.x, rc[q].y * e1.y);
                if (!((wq >> s1) & 1u)) b = 0.f;
                w0[q] = a; w1[q] = b;
                dacc[q] += a + b;
            }

            unsigned am0[4] = {__float_as_uint(w0[0]), __float_as_uint(w0[1]),
                               __float_as_uint(w1[0]), __float_as_uint(w1[1])};
            unsigned am1[4] = {__float_as_uint(w0[2]), __float_as_uint(w0[3]),
                               __float_as_uint(w1[2]), __float_as_uint(w1[3])};

#pragma unroll
            for (int nf = 0; nf < NFRAG; nf++) {
                unsigned b0 = hsu[c0 * HS + nf * 8 + gid];
                unsigned b1 = hsu[c1 * HS + nf * 8 + gid];
                MMA_TF32(acc[0][nf], am0[0], am0[1], am0[2], am0[3], b0, b1);
                MMA_TF32(acc[1][nf], am1[0], am1[1], am1[2], am1[3], b0, b1);
            }
        }
        __syncthreads();
    }

    // quad-lane reduce of denominators
#pragma unroll
    for (int q = 0; q < 4; q++) {
        dacc[q] += __shfl_xor_sync(0xffffffffu, dacc[q], 1);
        dacc[q] += __shfl_xor_sync(0xffffffffu, dacc[q], 2);
    }

    if (JSPLIT == 1) {
        if (tid4 == 0) {
#pragma unroll
            for (int q = 0; q < 4; q++) dens[rbase + q * 8] = dacc[q];
        }
        __syncthreads();
        float iv[4];
#pragma unroll
        for (int q = 0; q < 4; q++) iv[q] = 1.f / dens[rbase + q * 8];
#pragma unroll
        for (int mf = 0; mf < 2; mf++)
#pragma unroll
            for (int nf = 0; nf < NFRAG; nf++) {
                int col = head * F + fofs + nf * 8 + tid4 * 2;
                int ra = i0 + rbase + mf * 16;
                float2 v0 = make_float2(acc[mf][nf][0] * iv[mf * 2],
                                        acc[mf][nf][1] * iv[mf * 2]);
                float2 v1 = make_float2(acc[mf][nf][2] * iv[mf * 2 + 1],
                                        acc[mf][nf][3] * iv[mf * 2 + 1]);
                *reinterpret_cast<float2*>(&out[(size_t)ra * HF + col]) = v0;
                *reinterpret_cast<float2*>(&out[(size_t)(ra + 8) * HF + col]) = v1;
            }
    } else {
        if (fs == 0 && tid4 == 0) {
#pragma unroll
            for (int q = 0; q < 4; q++)
                pden[((size_t)js * HH + head) * NN + i0 + rbase + q * 8] = dacc[q];
        }
        float* pb = pnum + (size_t)js * NN * HF;
#pragma unroll
        for (int mf = 0; mf < 2; mf++)
#pragma unroll
            for (int nf = 0; nf < NFRAG; nf++) {
                int col = head * F + fofs + nf * 8 + tid4 * 2;
                int ra = i0 + rbase + mf * 16;
                float2 v0 = make_float2(acc[mf][nf][0], acc[mf][nf][1]);
                float2 v1 = make_float2(acc[mf][nf][2], acc[mf][nf][3]);
                *reinterpret_cast<float2*>(&pb[(size_t)ra * HF + col]) = v0;
                *reinterpret_cast<float2*>(&pb[(size_t)(ra + 8) * HF + col]) = v1;
            }
    }
}

// combine j-split partials: out[n][c] = sum_js pnum / sum_js pden
template<int F, int JS>
__global__ void combine_k(const float* __restrict__ p, const float* __restrict__ dp,
                          float* __restrict__ out) {
    constexpr int HF = HH * F;
    int n = blockIdx.x;
    for (int c = threadIdx.x; c < HF; c += blockDim.x) {
        int head = c / F;
        float d = 0.f, v = 0.f;
#pragma unroll
        for (int z = 0; z < JS; z++) {
            d += dp[((size_t)z * HH + head) * NN + n];
            v += p[(size_t)z * NN * HF + (size_t)n * HF + c];
        }
        out[(size_t)n * HF + c] = v / d;
    }
}

// ---------------- batchnorm stats ----------------
template<int C>
__global__ void bnstats_k(const float* __restrict__ y, float* __restrict__ stats) {
    int c = blockIdx.x;
    int t = threadIdx.x;  // 256
    float s = 0.f, q = 0.f;
    for (int r = t; r < NN; r += 256) {
        float v = y[r * C + c];
        s += v; q = fmaf(v, v, q);
    }
    __shared__ float ss[256], qq[256];
    ss[t] = s; qq[t] = q;
    __syncthreads();
#pragma unroll
    for (int o = 128; o > 0; o >>= 1) {
        if (t < o) { ss[t] += ss[t + o]; qq[t] += qq[t + o]; }
        __syncthreads();
    }
    if (t == 0) {
        float mean = ss[0] / (float)NN;
        float var  = qq[0] / (float)NN - mean * mean;
        stats[c]       = mean;
        stats[128 + c] = rsqrtf(var + 1e-5f);
    }
}

// ---------------- normalize + affine + ELU ----------------
template<int C>
__global__ void bnelu_k(const float* __restrict__ y, const float* __restrict__ stats,
                        const float* __restrict__ g, const float* __restrict__ b,
                        float* __restrict__ out) {
    int idx = blockIdx.x * blockDim.x + threadIdx.x;
    if (idx >= NN * C) return;
    int c = idx % C;
    float v = (y[idx] - stats[c]) * stats[128 + c];
    v = fmaf(v, g[c], b[c]);
    out[idx] = v > 0.f ? v : expm1f(v);
}

// ---------------- launch ----------------
extern "C" void kernel_launch(void* const* d_in, const int* in_sizes, int n_in,
                              void* d_out, int out_size) {
    const float* x   = (const float*)d_in[0];
    const int*   adj = (const int*)d_in[1];
    const float* W1  = (const float*)d_in[2];
    const float* a1s = (const float*)d_in[3];
    const float* a1d = (const float*)d_in[4];
    const float* lw1 = (const float*)d_in[5];
    const float* lb1 = (const float*)d_in[6];
    const float* g1  = (const float*)d_in[7];
    const float* be1 = (const float*)d_in[8];
    const float* W2  = (const float*)d_in[9];
    const float* a2s = (const float*)d_in[10];
    const float* a2d = (const float*)d_in[11];
    const float* lw2 = (const float*)d_in[12];
    const float* lb2 = (const float*)d_in[13];
    const float* g2  = (const float*)d_in[14];
    const float* be2 = (const float*)d_in[15];
    float* out = (float*)d_out;

    float *h1, *x1, *y1, *x2, *h2, *x3, *y2, *stats, *part, *dpart;
    float2 *rowc1, *evq1, *rowc2, *evq2;
    unsigned *bitsp, *spAh, *spAl, *spBh, *spBl;
    cudaGetSymbolAddress((void**)&h1,  g_h1);
    cudaGetSymbolAddress((void**)&x1,  g_x1);
    cudaGetSymbolAddress((void**)&y1,  g_y1);
    cudaGetSymbolAddress((void**)&x2,  g_x2);
    cudaGetSymbolAddress((void**)&h2,  g_h2);
    cudaGetSymbolAddress((void**)&x3,  g_x3);
    cudaGetSymbolAddress((void**)&y2,  g_y2);
    cudaGetSymbolAddress((void**)&rowc1, g_rowc1);
    cudaGetSymbolAddress((void**)&evq1,  g_evq1);
    cudaGetSymbolAddress((void**)&rowc2, g_rowc2);
    cudaGetSymbolAddress((void**)&evq2,  g_evq2);
    cudaGetSymbolAddress((void**)&stats, g_stats);
    cudaGetSymbolAddress((void**)&part,  g_part);
    cudaGetSymbolAddress((void**)&dpart, g_dpart);
    cudaGetSymbolAddress((void**)&bitsp, g_adjbits);
    cudaGetSymbolAddress((void**)&spAh, g_spAh);
    cudaGetSymbolAddress((void**)&spAl, g_spAl);
    cudaGetSymbolAddress((void**)&spBh, g_spBh);
    cudaGetSymbolAddress((void**)&spBl, g_spBl);

    // pack adjacency to bits
    pack_adj_k<<<(NN * NN) / 256, 256>>>(adj, bitsp);

    // ---- layer 1 GAT ----
    presplit_k<<<(NN * 512) / 256, 256>>>(x, spAh, spAl, NN * 512);
    presplit_k<<<(512 * 512) / 256, 256>>>(W1, spBh, spBl, 512 * 512);
    gemm3t_pre_k<<<dim3(512 / 64, NN / 128), 256>>>(spAh, spAl, spBh, spBl, nullptr, h1, NN, 512, 512);
    esed_k<128><<<NN, 128>>>(h1, a1s, a1d, rowc1, evq1);
    // F=128: FSPLIT=2 x JSPLIT=2 -> grid 32x4x4 = 512 blocks of 128 thr
    attn_mma_k<128, 64, 2, 2><<<dim3(NN / 128, HH, 4), 128>>>(h1, rowc1, evq1, bitsp, nullptr, part, dpart);
    combine_k<128, 2><<<NN, 256>>>(part, dpart, x1);

    // ---- MLP 1 + BN + ELU ----
    presplit_k<<<(NN * 512) / 256, 256>>>(x1, spAh, spAl, NN * 512);
    presplit_k<<<(512 * 64) / 256, 256>>>(lw1, spBh, spBl, 512 * 64);
    gemm3t_pre_k<<<dim3(1, NN / 128), 256>>>(spAh, spAl, spBh, spBl, lb1, y1, NN, 64, 512);
    bnstats_k<64><<<64, 256>>>(y1, stats);
    bnelu_k<64><<<(NN * 64) / 256, 256>>>(y1, stats, g1, be1, x2);

    // ---- layer 2 GAT ----
    gemm_k<128, 64, 16, 8, 4><<<dim3(2, NN / 128), 256>>>(x2, W2, nullptr, h2, NN, 128, 64);
    esed_k<32><<<NN, 128>>>(h2, a2s, a2d, rowc2, evq2);
    // F=FE=32: JSPLIT=4 -> grid 32x4x4 = 512 blocks of 128 thr
    attn_mma_k<32, 32, 1, 4><<<dim3(NN / 128, HH, 4), 128>>>(h2, rowc2, evq2, bitsp, nullptr, part, dpart);
    combine_k<32, 4><<<NN, 128>>>(part, dpart, x3);

    // ---- MLP 2 + BN + ELU ----
    gemm_k<64, 16, 16, 4, 1><<<dim3(1, NN / 64), 256>>>(x3, lw2, lb2, y2, NN, 16, 128);
    bnstats_k<16><<<16, 256>>>(y2, stats);
    bnelu_k<16><<<(NN * 16) / 256, 256>>>(y2, stats, g2, be2, out);
}

// round 13
// speedup vs baseline: 1.0609x; 1.0299x over previous
#include <cuda_runtime.h>
#include <cuda_bf16.h>
#include <cstdint>

#define NN 4096
#define HH 4

// ---------------- scratch ----------------
__device__ float  g_h1 [NN * 512];
__device__ float  g_y1 [NN * 64];
__device__ float  g_x2 [NN * 64];
__device__ float  g_h2 [NN * 128];
__device__ float  g_x3 [NN * 128];
__device__ float  g_y2 [NN * 16];
__device__ float2 g_rowc1[HH * NN];   // {e^es, e^{0.2es}}
__device__ float2 g_evq1 [HH * NN];   // {e^ed, e^{0.2ed}}
__device__ float2 g_rowc2[HH * NN];
__device__ float2 g_evq2 [HH * NN];
__device__ unsigned g_adjbits[NN * (NN / 32)];
__device__ float  g_stats[256];
__device__ float  g_part [2 * NN * 512];   // attn partial numerators
__device__ float  g_dpart[4 * HH * NN];    // partial denominators
__device__ unsigned g_spAh[NN * 512], g_spAl[NN * 512];   // pre-split A (tf32 hi/lo)
__device__ unsigned g_spBh[512 * 512], g_spBl[512 * 512]; // pre-split B

// ---------------- helpers ----------------
__device__ __forceinline__ unsigned smem_u32(const void* p) {
    return (unsigned)__cvta_generic_to_shared(p);
}
#define CP_ASYNC16(dst, src) \
    asm volatile("cp.async.cg.shared.global [%0], [%1], 16;" :: "r"(dst), "l"(src))
#define CP_ASYNC8(dst, src) \
    asm volatile("cp.async.ca.shared.global [%0], [%1], 8;" :: "r"(dst), "l"(src))
#define CP_COMMIT() asm volatile("cp.async.commit_group;")
#define CP_WAIT1()  asm volatile("cp.async.wait_group 1;")
#define CP_WAIT0()  asm volatile("cp.async.wait_group 0;")

#define MMA_TF32(acc, a0, a1, a2, a3, b0, b1)                                   \
    asm volatile(                                                               \
        "mma.sync.aligned.m16n8k8.row.col.f32.tf32.tf32.f32 "                   \
        "{%0,%1,%2,%3}, {%4,%5,%6,%7}, {%8,%9}, {%0,%1,%2,%3};"                 \
        : "+f"(acc[0]), "+f"(acc[1]), "+f"(acc[2]), "+f"(acc[3])                \
        : "r"(a0), "r"(a1), "r"(a2), "r"(a3), "r"(b0), "r"(b1))

__device__ __forceinline__ void split_tf32(float v, unsigned& h, unsigned& l) {
    unsigned hv;
    asm("cvt.rna.tf32.f32 %0, %1;" : "=r"(hv) : "f"(v));
    float lo = v - __uint_as_float(hv);
    unsigned lv;
    asm("cvt.rna.tf32.f32 %0, %1;" : "=r"(lv) : "f"(lo));
    h = hv; l = lv;
}

// ---------------- adjacency packing ----------------
__global__ void pack_adj_k(const int* __restrict__ adj, unsigned* __restrict__ bits) {
    int gid = blockIdx.x * blockDim.x + threadIdx.x;
    unsigned pred = adj[gid] > 0 ? 1u : 0u;
    unsigned word = __ballot_sync(0xffffffffu, pred);
    if ((threadIdx.x & 31) == 0) bits[gid >> 5] = word;
}

// ---------------- tf32 hi/lo pre-split (elementwise) ----------------
__global__ void presplit_k(const float* __restrict__ a, unsigned* __restrict__ hi,
                           unsigned* __restrict__ lo, int n) {
    int i = blockIdx.x * blockDim.x + threadIdx.x;
    if (i >= n) return;
    unsigned h, l;
    split_tf32(a[i], h, l);
    hi[i] = h; lo[i] = l;
}

// ---------------- 3xTF32 MMA GEMM on pre-split inputs, double-buffered ----------------
// C = A@B (+bias). BM=128,BN=64,BK=32; 8 warps (4m x 2n); 2-stage cp.async pipeline.
__global__ __launch_bounds__(256, 2)
void gemm3t_pre_k(const unsigned* __restrict__ Agh, const unsigned* __restrict__ Agl,
                  const unsigned* __restrict__ Bgh, const unsigned* __restrict__ Bgl,
                  const float* __restrict__ bias, float* __restrict__ C,
                  int M, int N, int K) {
    constexpr int BM = 128, BN = 64, BK = 32;
    constexpr int AS = BK + 4;
    constexpr int BS = BN + 4;
    constexpr int AW = BM * AS;       // words per A plane
    constexpr int BW = BK * BS;
    constexpr int STG = 2 * AW + 2 * BW;   // words per stage

    extern __shared__ unsigned sm[];
    // stage s: [Ah | Al | Bh | Bl]

    int t = threadIdx.x;
    int wid = t >> 5, lane = t & 31;
    int gid = lane >> 2, tid4 = lane & 3;
    int m0 = blockIdx.y * BM, n0 = blockIdx.x * BN;
    int wm = (wid & 3) * 32, wn = (wid >> 2) * 32;

    float acc[2][4][4];
#pragma unroll
    for (int mf = 0; mf < 2; mf++)
#pragma unroll
        for (int nf = 0; nf < 4; nf++)
#pragma unroll
            for (int c = 0; c < 4; c++) acc[mf][nf][c] = 0.f;

    auto load_tile = [&](int st, int k0) {
        unsigned* Ah = sm + st * STG;
        unsigned* Al = Ah + AW;
        unsigned* Bh = Al + AW;
        unsigned* Bl = Bh + BW;
#pragma unroll
        for (int i = 0; i < (BM * BK) / (256 * 4); i++) {
            int e = (t + i * 256) * 4;
            int m = e / BK, k = e % BK;
            CP_ASYNC16(smem_u32(&Ah[m * AS + k]), Agh + (size_t)(m0 + m) * K + k0 + k);
            CP_ASYNC16(smem_u32(&Al[m * AS + k]), Agl + (size_t)(m0 + m) * K + k0 + k);
        }
#pragma unroll
        for (int i = 0; i < (BK * BN) / (256 * 4); i++) {
            int e = (t + i * 256) * 4;
            int k = e / BN, n = e % BN;
            CP_ASYNC16(smem_u32(&Bh[k * BS + n]), Bgh + (size_t)(k0 + k) * N + n0 + n);
            CP_ASYNC16(smem_u32(&Bl[k * BS + n]), Bgl + (size_t)(k0 + k) * N + n0 + n);
        }
        CP_COMMIT();
    };

    int NKT = K / BK;
    load_tile(0, 0);

    for (int tt = 0; tt < NKT; tt++) {
        int st = tt & 1;
        if (tt + 1 < NKT) { load_tile(st ^ 1, (tt + 1) * BK); CP_WAIT1(); }
        else             { CP_WAIT0(); }
        __syncthreads();

        const unsigned* Ah = sm + st * STG;
        const unsigned* Al = Ah + AW;
        const unsigned* Bh = Al + AW;
        const unsigned* Bl = Bh + BW;

#pragma unroll
        for (int k8 = 0; k8 < BK / 8; k8++) {
            unsigned ah[2][4], al[2][4];
#pragma unroll
            for (int mf = 0; mf < 2; mf++) {
                int r0 = wm + mf * 16 + gid;
                ah[mf][0] = Ah[r0 * AS + k8 * 8 + tid4];
                ah[mf][1] = Ah[(r0 + 8) * AS + k8 * 8 + tid4];
                ah[mf][2] = Ah[r0 * AS + k8 * 8 + tid4 + 4];
                ah[mf][3] = Ah[(r0 + 8) * AS + k8 * 8 + tid4 + 4];
                al[mf][0] = Al[r0 * AS + k8 * 8 + tid4];
                al[mf][1] = Al[(r0 + 8) * AS + k8 * 8 + tid4];
                al[mf][2] = Al[r0 * AS + k8 * 8 + tid4 + 4];
                al[mf][3] = Al[(r0 + 8) * AS + k8 * 8 + tid4 + 4];
            }
#pragma unroll
            for (int nf = 0; nf < 4; nf++) {
                int cb = wn + nf * 8 + gid;
                unsigned bh0 = Bh[(k8 * 8 + tid4) * BS + cb];
                unsigned bh1 = Bh[(k8 * 8 + tid4 + 4) * BS + cb];
                unsigned bl0 = Bl[(k8 * 8 + tid4) * BS + cb];
                unsigned bl1 = Bl[(k8 * 8 + tid4 + 4) * BS + cb];
#pragma unroll
                for (int mf = 0; mf < 2; mf++) {
                    MMA_TF32(acc[mf][nf], ah[mf][0], ah[mf][1], ah[mf][2], ah[mf][3], bh0, bh1);
                    MMA_TF32(acc[mf][nf], ah[mf][0], ah[mf][1], ah[mf][2], ah[mf][3], bl0, bl1);
                    MMA_TF32(acc[mf][nf], al[mf][0], al[mf][1], al[mf][2], al[mf][3], bh0, bh1);
                }
            }
        }
        __syncthreads();
    }

#pragma unroll
    for (int mf = 0; mf < 2; mf++) {
        int r0 = m0 + wm + mf * 16 + gid;
#pragma unroll
        for (int nf = 0; nf < 4; nf++) {
            int col = n0 + wn + nf * 8 + tid4 * 2;
            float b0 = bias ? bias[col] : 0.f;
            float b1 = bias ? bias[col + 1] : 0.f;
            float2 v0 = make_float2(acc[mf][nf][0] + b0, acc[mf][nf][1] + b1);
            float2 v1 = make_float2(acc[mf][nf][2] + b0, acc[mf][nf][3] + b1);
            *reinterpret_cast<float2*>(&C[(size_t)r0 * N + col]) = v0;
            *reinterpret_cast<float2*>(&C[(size_t)(r0 + 8) * N + col]) = v1;
        }
    }
}

// ---------------- generic fp32 tiled GEMM (small cases) ----------------
template<int BM, int BN, int BK, int TM, int TN>
__global__ void gemm_k(const float* __restrict__ A, const float* __restrict__ B,
                       const float* __restrict__ bias, float* __restrict__ C,
                       int M, int N, int K) {
    __shared__ float As[BK][BM];
    __shared__ float Bs[BK][BN];
    constexpr int TX = BN / TN;
    int tid = threadIdx.x;
    int tx = tid % TX, ty = tid / TX;
    int m0 = blockIdx.y * BM, n0 = blockIdx.x * BN;
    float acc[TM][TN];
#pragma unroll
    for (int i = 0; i < TM; i++)
#pragma unroll
        for (int j = 0; j < TN; j++) acc[i][j] = 0.f;

    for (int k0 = 0; k0 < K; k0 += BK) {
#pragma unroll
        for (int idx = tid; idx < BM * BK; idx += 256) {
            int m = idx / BK, k = idx % BK;
            As[k][m] = A[(m0 + m) * K + k0 + k];
        }
#pragma unroll
        for (int idx = tid; idx < BK * BN; idx += 256) {
            int k = idx / BN, n = idx % BN;
            Bs[k][n] = B[(k0 + k) * N + n0 + n];
        }
        __syncthreads();
#pragma unroll
        for (int k = 0; k < BK; k++) {
            float ra[TM], rb[TN];
#pragma unroll
            for (int i = 0; i < TM; i++) ra[i] = As[k][ty * TM + i];
#pragma unroll
            for (int j = 0; j < TN; j++) rb[j] = Bs[k][tx * TN + j];
#pragma unroll
            for (int i = 0; i < TM; i++)
#pragma unroll
                for (int j = 0; j < TN; j++) acc[i][j] = fmaf(ra[i], rb[j], acc[i][j]);
        }
        __syncthreads();
    }
#pragma unroll
    for (int i = 0; i < TM; i++)
#pragma unroll
        for (int j = 0; j < TN; j++) {
            float v = acc[i][j];
            if (bias) v += bias[n0 + tx * TN + j];
            C[(m0 + ty * TM + i) * N + n0 + tx * TN + j] = v;
        }
}

// ---------------- per-node logits -> factorized exponentials ----------------
template<int F>
__global__ void esed_k(const float* __restrict__ h, const float* __restrict__ asv,
                       const float* __restrict__ adv, float2* __restrict__ rowc,
                       float2* __restrict__ evq) {
    int n = blockIdx.x;
    int t = threadIdx.x;  // 128
    __shared__ float rs[128], rd[128];
    for (int hd = 0; hd < HH; hd++) {
        float vs = 0.f, vd = 0.f;
        for (int f = t; f < F; f += 128) {
            float hv = h[n * (HH * F) + hd * F + f];
            vs = fmaf(hv, asv[hd * F + f], vs);
            vd = fmaf(hv, adv[hd * F + f], vd);
        }
        rs[t] = vs; rd[t] = vd;
        __syncthreads();
#pragma unroll
        for (int s = 64; s > 0; s >>= 1) {
            if (t < s) { rs[t] += rs[t + s]; rd[t] += rd[t + s]; }
            __syncthreads();
        }
        if (t == 0) {
            float es0 = rs[0], ed0 = rd[0];
            rowc[hd * NN + n] = make_float2(expf(es0), expf(0.2f * es0));
            evq [hd * NN + n] = make_float2(expf(ed0), expf(0.2f * ed0));
        }
        __syncthreads();
    }
}

// ---------------- fused masked-softmax GAT aggregation (tf32 mma) ----------------
template<int F, int FE, int FSPLIT, int JSPLIT>
__global__ __launch_bounds__(128, 4)
void attn_mma_k(const float* __restrict__ h, const float2* __restrict__ rowc,
                const float2* __restrict__ evq, const unsigned* __restrict__ bits,
                float* __restrict__ out, float* __restrict__ pnum,
                float* __restrict__ pden) {
    constexpr int IT = 128;
    constexpr int JT = 64;
    constexpr int HS = FE + 8;
    constexpr int NFRAG = FE / 8;
    constexpr int HF = HH * F;
    constexpr int NV = FE / 4;
    constexpr int JSPAN = NN / JSPLIT;
    constexpr int NT = JSPAN / JT;

    __shared__ float  hs[2][JT * HS];
    __shared__ float2 evq_s[2][JT];
    __shared__ uint2  bits_s[2][IT];
    __shared__ float2 rowc_s[IT];
    __shared__ float  dens[IT];

    int t = threadIdx.x;           // 0..127
    int wid = t >> 5, lane = t & 31;
    int gid = lane >> 2, tid4 = lane & 3;
    int head = blockIdx.y;
    int i0 = blockIdx.x * IT;
    int zz = blockIdx.z;
    int fs = zz % FSPLIT, js = zz / FSPLIT;
    int fofs = fs * FE;
    int jbeg = js * JSPAN;

    int rbase = wid * 32 + gid;

    rowc_s[t] = rowc[head * NN + i0 + t];

    const float* hbase = h + head * F + fofs;
    const unsigned* bbase = bits + (size_t)i0 * (NN / 32);

    auto load_tile = [&](int st, int j0) {
#pragma unroll
        for (int idx = t; idx < JT * NV; idx += 128) {
            int jj = idx / NV, fv = idx % NV;
            CP_ASYNC16(smem_u32(&hs[st][jj * HS + fv * 4]),
                       hbase + (size_t)(j0 + jj) * HF + fv * 4);
        }
        if (t < JT) CP_ASYNC8(smem_u32(&evq_s[st][t]), evq + head * NN + j0 + t);
        CP_ASYNC8(smem_u32(&bits_s[st][t]), bbase + (size_t)t * (NN / 32) + (j0 >> 5));
        CP_COMMIT();
    };

    float acc[2][NFRAG][4];
#pragma unroll
    for (int mf = 0; mf < 2; mf++)
#pragma unroll
        for (int nf = 0; nf < NFRAG; nf++)
#pragma unroll
            for (int c = 0; c < 4; c++) acc[mf][nf][c] = 0.f;
    float dacc[4] = {0.f, 0.f, 0.f, 0.f};

    load_tile(0, jbeg);

    for (int tt = 0; tt < NT; tt++) {
        int st = tt & 1;
        if (tt + 1 < NT) { load_tile(st ^ 1, jbeg + (tt + 1) * JT); CP_WAIT1(); }
        else             { CP_WAIT0(); }
        __syncthreads();

        float2 rc[4];
        uint2  bw[4];
#pragma unroll
        for (int q = 0; q < 4; q++) {
            rc[q] = rowc_s[rbase + q * 8];
            bw[q] = bits_s[st][rbase + q * 8];
        }
        const unsigned* hsu = reinterpret_cast<const unsigned*>(hs[st]);

#pragma unroll
        for (int k = 0; k < JT / 8; k++) {
            int c0 = k * 8 + tid4, c1 = c0 + 4;
            float2 e0 = evq_s[st][c0], e1 = evq_s[st][c1];
            int s0 = c0 & 31, s1 = c1 & 31;

            float w0[4], w1[4];
#pragma unroll
            for (int q = 0; q < 4; q++) {
                unsigned wq = (k < 4) ? bw[q].x : bw[q].y;
                float a = fmaxf(rc[q].x * e0.x, rc[q].y * e0.y);
                if (!((wq >> s0) & 1u)) a = 0.f;
                float b = fmaxf(rc[q].x * e1.x, rc[q].y * e1.y);
                if (!((wq >> s1) & 1u)) b = 0.f;
                w0[q] = a; w1[q] = b;
                dacc[q] += a + b;
            }

            unsigned am0[4] = {__float_as_uint(w0[0]), __float_as_uint(w0[1]),
                               __float_as_uint(w1[0]), __float_as_uint(w1[1])};
            unsigned am1[4] = {__float_as_uint(w0[2]), __float_as_uint(w0[3]),
                               __float_as_uint(w1[2]), __float_as_uint(w1[3])};

#pragma unroll
            for (int nf = 0; nf < NFRAG; nf++) {
                unsigned b0 = hsu[c0 * HS + nf * 8 + gid];
                unsigned b1 = hsu[c1 * HS + nf * 8 + gid];
                MMA_TF32(acc[0][nf], am0[0], am0[1], am0[2], am0[3], b0, b1);
                MMA_TF32(acc[1][nf], am1[0], am1[1], am1[2], am1[3], b0, b1);
            }
        }
        __syncthreads();
    }

#pragma unroll
    for (int q = 0; q < 4; q++) {
        dacc[q] += __shfl_xor_sync(0xffffffffu, dacc[q], 1);
        dacc[q] += __shfl_xor_sync(0xffffffffu, dacc[q], 2);
    }

    if (JSPLIT == 1) {
        if (tid4 == 0) {
#pragma unroll
            for (int q = 0; q < 4; q++) dens[rbase + q * 8] = dacc[q];
        }
        __syncthreads();
        float iv[4];
#pragma unroll
        for (int q = 0; q < 4; q++) iv[q] = 1.f / dens[rbase + q * 8];
#pragma unroll
        for (int mf = 0; mf < 2; mf++)
#pragma unroll
            for (int nf = 0; nf < NFRAG; nf++) {
                int col = head * F + fofs + nf * 8 + tid4 * 2;
                int ra = i0 + rbase + mf * 16;
                float2 v0 = make_float2(acc[mf][nf][0] * iv[mf * 2],
                                        acc[mf][nf][1] * iv[mf * 2]);
                float2 v1 = make_float2(acc[mf][nf][2] * iv[mf * 2 + 1],
                                        acc[mf][nf][3] * iv[mf * 2 + 1]);
                *reinterpret_cast<float2*>(&out[(size_t)ra * HF + col]) = v0;
                *reinterpret_cast<float2*>(&out[(size_t)(ra + 8) * HF + col]) = v1;
            }
    } else {
        if (fs == 0 && tid4 == 0) {
#pragma unroll
            for (int q = 0; q < 4; q++)
                pden[((size_t)js * HH + head) * NN + i0 + rbase + q * 8] = dacc[q];
        }
        float* pb = pnum + (size_t)js * NN * HF;
#pragma unroll
        for (int mf = 0; mf < 2; mf++)
#pragma unroll
            for (int nf = 0; nf < NFRAG; nf++) {
                int col = head * F + fofs + nf * 8 + tid4 * 2;
                int ra = i0 + rbase + mf * 16;
                float2 v0 = make_float2(acc[mf][nf][0], acc[mf][nf][1]);
                float2 v1 = make_float2(acc[mf][nf][2], acc[mf][nf][3]);
                *reinterpret_cast<float2*>(&pb[(size_t)ra * HF + col]) = v0;
                *reinterpret_cast<float2*>(&pb[(size_t)(ra + 8) * HF + col]) = v1;
            }
    }
}

// combine j-split partials: v = sum(pnum)/sum(pden).
// SPLITOUT: write tf32 hi/lo planes (for feeding gemm3t_pre) instead of floats.
template<int F, int JS, bool SPLITOUT>
__global__ void combine_k(const float* __restrict__ p, const float* __restrict__ dp,
                          float* __restrict__ out, unsigned* __restrict__ ohi,
                          unsigned* __restrict__ olo) {
    constexpr int HF = HH * F;
    int n = blockIdx.x;
    for (int c = threadIdx.x; c < HF; c += blockDim.x) {
        int head = c / F;
        float d = 0.f, v = 0.f;
#pragma unroll
        for (int z = 0; z < JS; z++) {
            d += dp[((size_t)z * HH + head) * NN + n];
            v += p[(size_t)z * NN * HF + (size_t)n * HF + c];
        }
        v /= d;
        if (SPLITOUT) {
            unsigned h, l;
            split_tf32(v, h, l);
            ohi[(size_t)n * HF + c] = h;
            olo[(size_t)n * HF + c] = l;
        } else {
            out[(size_t)n * HF + c] = v;
        }
    }
}

// ---------------- batchnorm stats ----------------
template<int C>
__global__ void bnstats_k(const float* __restrict__ y, float* __restrict__ stats) {
    int c = blockIdx.x;
    int t = threadIdx.x;  // 256
    float s = 0.f, q = 0.f;
    for (int r = t; r < NN; r += 256) {
        float v = y[r * C + c];
        s += v; q = fmaf(v, v, q);
    }
    __shared__ float ss[256], qq[256];
    ss[t] = s; qq[t] = q;
    __syncthreads();
#pragma unroll
    for (int o = 128; o > 0; o >>= 1) {
        if (t < o) { ss[t] += ss[t + o]; qq[t] += qq[t + o]; }
        __syncthreads();
    }
    if (t == 0) {
        float mean = ss[0] / (float)NN;
        float var  = qq[0] / (float)NN - mean * mean;
        stats[c]       = mean;
        stats[128 + c] = rsqrtf(var + 1e-5f);
    }
}

// ---------------- normalize + affine + ELU ----------------
template<int C>
__global__ void bnelu_k(const float* __restrict__ y, const float* __restrict__ stats,
                        const float* __restrict__ g, const float* __restrict__ b,
                        float* __restrict__ out) {
    int idx = blockIdx.x * blockDim.x + threadIdx.x;
    if (idx >= NN * C) return;
    int c = idx % C;
    float v = (y[idx] - stats[c]) * stats[128 + c];
    v = fmaf(v, g[c], b[c]);
    out[idx] = v > 0.f ? v : expm1f(v);
}

// ---------------- launch ----------------
extern "C" void kernel_launch(void* const* d_in, const int* in_sizes, int n_in,
                              void* d_out, int out_size) {
    const float* x   = (const float*)d_in[0];
    const int*   adj = (const int*)d_in[1];
    const float* W1  = (const float*)d_in[2];
    const float* a1s = (const float*)d_in[3];
    const float* a1d = (const float*)d_in[4];
    const float* lw1 = (const float*)d_in[5];
    const float* lb1 = (const float*)d_in[6];
    const float* g1  = (const float*)d_in[7];
    const float* be1 = (const float*)d_in[8];
    const float* W2  = (const float*)d_in[9];
    const float* a2s = (const float*)d_in[10];
    const float* a2d = (const float*)d_in[11];
    const float* lw2 = (const float*)d_in[12];
    const float* lb2 = (const float*)d_in[13];
    const float* g2  = (const float*)d_in[14];
    const float* be2 = (const float*)d_in[15];
    float* out = (float*)d_out;

    float *h1, *y1, *x2, *h2, *x3, *y2, *stats, *part, *dpart;
    float2 *rowc1, *evq1, *rowc2, *evq2;
    unsigned *bitsp, *spAh, *spAl, *spBh, *spBl;
    cudaGetSymbolAddress((void**)&h1,  g_h1);
    cudaGetSymbolAddress((void**)&y1,  g_y1);
    cudaGetSymbolAddress((void**)&x2,  g_x2);
    cudaGetSymbolAddress((void**)&h2,  g_h2);
    cudaGetSymbolAddress((void**)&x3,  g_x3);
    cudaGetSymbolAddress((void**)&y2,  g_y2);
    cudaGetSymbolAddress((void**)&rowc1, g_rowc1);
    cudaGetSymbolAddress((void**)&evq1,  g_evq1);
    cudaGetSymbolAddress((void**)&rowc2, g_rowc2);
    cudaGetSymbolAddress((void**)&evq2,  g_evq2);
    cudaGetSymbolAddress((void**)&stats, g_stats);
    cudaGetSymbolAddress((void**)&part,  g_part);
    cudaGetSymbolAddress((void**)&dpart, g_dpart);
    cudaGetSymbolAddress((void**)&bitsp, g_adjbits);
    cudaGetSymbolAddress((void**)&spAh, g_spAh);
    cudaGetSymbolAddress((void**)&spAl, g_spAl);
    cudaGetSymbolAddress((void**)&spBh, g_spBh);
    cudaGetSymbolAddress((void**)&spBl, g_spBl);

    // dynamic smem for pipelined 3xtf32 gemm: 2 stages
    const int gemm_smem = 2 * (2 * 128 * 36 + 2 * 32 * 68) * 4;   // 108544 B
    cudaFuncSetAttribute(gemm3t_pre_k, cudaFuncAttributeMaxDynamicSharedMemorySize, gemm_smem);

    // pack adjacency to bits
    pack_adj_k<<<(NN * NN) / 256, 256>>>(adj, bitsp);

    // ---- layer 1 GAT ----
    presplit_k<<<(NN * 512) / 256, 256>>>(x, spAh, spAl, NN * 512);
    presplit_k<<<(512 * 512) / 256, 256>>>(W1, spBh, spBl, 512 * 512);
    gemm3t_pre_k<<<dim3(512 / 64, NN / 128), 256, gemm_smem>>>(spAh, spAl, spBh, spBl, nullptr, h1, NN, 512, 512);
    esed_k<128><<<NN, 128>>>(h1, a1s, a1d, rowc1, evq1);
    // F=128: FSPLIT=2 x JSPLIT=2 -> grid 32x4x4 = 512 blocks of 128 thr
    attn_mma_k<128, 64, 2, 2><<<dim3(NN / 128, HH, 4), 128>>>(h1, rowc1, evq1, bitsp, nullptr, part, dpart);
    // combine writes tf32 hi/lo planes of x1 directly (consumed only by lw1 GEMM)
    combine_k<128, 2, true><<<NN, 256>>>(part, dpart, nullptr, spAh, spAl);

    // ---- MLP 1 + BN + ELU ----
    presplit_k<<<(512 * 64) / 256, 256>>>(lw1, spBh, spBl, 512 * 64);
    gemm3t_pre_k<<<dim3(1, NN / 128), 256, gemm_smem>>>(spAh, spAl, spBh, spBl, lb1, y1, NN, 64, 512);
    bnstats_k<64><<<64, 256>>>(y1, stats);
    bnelu_k<64><<<(NN * 64) / 256, 256>>>(y1, stats, g1, be1, x2);

    // ---- layer 2 GAT ----
    gemm_k<128, 64, 16, 8, 4><<<dim3(2, NN / 128), 256>>>(x2, W2, nullptr, h2, NN, 128, 64);
    esed_k<32><<<NN, 128>>>(h2, a2s, a2d, rowc2, evq2);
    // F=FE=32: JSPLIT=4 -> grid 32x4x4 = 512 blocks of 128 thr
    attn_mma_k<32, 32, 1, 4><<<dim3(NN / 128, HH, 4), 128>>>(h2, rowc2, evq2, bitsp, nullptr, part, dpart);
    combine_k<32, 4, false><<<NN, 128>>>(part, dpart, x3, nullptr, nullptr);

    // ---- MLP 2 + BN + ELU ----
    gemm_k<64, 16, 16, 4, 1><<<dim3(1, NN / 64), 256>>>(x3, lw2, lb2, y2, NN, 16, 128);
    bnstats_k<16><<<16, 256>>>(y2, stats);
    bnelu_k<16><<<(NN * 16) / 256, 256>>>(y2, stats, g2, be2, out);
}

// round 14
// speedup vs baseline: 1.0652x; 1.0040x over previous
#include <cuda_runtime.h>
#include <cuda_bf16.h>
#include <cstdint>

#define NN 4096
#define HH 4

// ---------------- scratch ----------------
__device__ float  g_h1 [NN * 512];
__device__ float  g_y1 [NN * 64];
__device__ float  g_x2 [NN * 64];
__device__ float  g_h2 [NN * 128];
__device__ float  g_x3 [NN * 128];
__device__ float  g_y2 [NN * 16];
__device__ float2 g_rowc1[HH * NN];   // {e^es, e^{0.2es}}
__device__ float2 g_evq1 [HH * NN];   // {e^ed, e^{0.2ed}}
__device__ float2 g_rowc2[HH * NN];
__device__ float2 g_evq2 [HH * NN];
__device__ unsigned g_adjbits[NN * (NN / 32)];
__device__ float  g_stats[256];
__device__ float  g_part [2 * NN * 512];   // attn partial numerators
__device__ float  g_dpart[4 * HH * NN];    // partial denominators
__device__ unsigned g_spAh[NN * 512], g_spAl[NN * 512];   // tf32 planes (x / x1 hi,lo)
__device__ unsigned g_spBh[512 * 512], g_spBl[512 * 512]; // tf32 planes (W1 / lw1)
__device__ float  g_cvec[2 * HH * 512];    // cs1 | cd1  (W1-folded attention vectors)

// ---------------- helpers ----------------
__device__ __forceinline__ unsigned smem_u32(const void* p) {
    return (unsigned)__cvta_generic_to_shared(p);
}
#define CP_ASYNC16(dst, src) \
    asm volatile("cp.async.cg.shared.global [%0], [%1], 16;" :: "r"(dst), "l"(src))
#define CP_ASYNC8(dst, src) \
    asm volatile("cp.async.ca.shared.global [%0], [%1], 8;" :: "r"(dst), "l"(src))
#define CP_COMMIT() asm volatile("cp.async.commit_group;")
#define CP_WAIT1()  asm volatile("cp.async.wait_group 1;")
#define CP_WAIT0()  asm volatile("cp.async.wait_group 0;")

#define MMA_TF32(acc, a0, a1, a2, a3, b0, b1)                                   \
    asm volatile(                                                               \
        "mma.sync.aligned.m16n8k8.row.col.f32.tf32.tf32.f32 "                   \
        "{%0,%1,%2,%3}, {%4,%5,%6,%7}, {%8,%9}, {%0,%1,%2,%3};"                 \
        : "+f"(acc[0]), "+f"(acc[1]), "+f"(acc[2]), "+f"(acc[3])                \
        : "r"(a0), "r"(a1), "r"(a2), "r"(a3), "r"(b0), "r"(b1))

__device__ __forceinline__ void split_tf32(float v, unsigned& h, unsigned& l) {
    unsigned hv;
    asm("cvt.rna.tf32.f32 %0, %1;" : "=r"(hv) : "f"(v));
    float lo = v - __uint_as_float(hv);
    unsigned lv;
    asm("cvt.rna.tf32.f32 %0, %1;" : "=r"(lv) : "f"(lo));
    h = hv; l = lv;
}

// ---------------- adjacency packing ----------------
__global__ void pack_adj_k(const int* __restrict__ adj, unsigned* __restrict__ bits) {
    int gid = blockIdx.x * blockDim.x + threadIdx.x;
    unsigned pred = adj[gid] > 0 ? 1u : 0u;
    unsigned word = __ballot_sync(0xffffffffu, pred);
    if ((threadIdx.x & 31) == 0) bits[gid >> 5] = word;
}

// ---------------- tf32 rna pre-round (single plane, unbiased) ----------------
__global__ void preround_k(const float* __restrict__ a, unsigned* __restrict__ hi, int n) {
    int i = blockIdx.x * blockDim.x + threadIdx.x;
    if (i >= n) return;
    unsigned h;
    asm("cvt.rna.tf32.f32 %0, %1;" : "=r"(h) : "f"(a[i]));
    hi[i] = h;
}

// ---------------- tf32 hi/lo pre-split (elementwise) ----------------
__global__ void presplit_k(const float* __restrict__ a, unsigned* __restrict__ hi,
                           unsigned* __restrict__ lo, int n) {
    int i = blockIdx.x * blockDim.x + threadIdx.x;
    if (i >= n) return;
    unsigned h, l;
    split_tf32(a[i], h, l);
    hi[i] = h; lo[i] = l;
}

// ---------------- fold attention vectors through W1: c[hd][k] = sum_f W1[k][hd*F+f]*a[hd][f]
__global__ void cvec_k(const float* __restrict__ W, const float* __restrict__ as,
                       const float* __restrict__ ad, float* __restrict__ cvec,
                       int K, int F) {
    int idx = blockIdx.x * blockDim.x + threadIdx.x;   // over K*HH
    if (idx >= K * HH) return;
    int k = idx / HH, hd = idx % HH;
    float vs = 0.f, vd = 0.f;
    const float* wr = W + (size_t)k * (HH * F) + hd * F;
    for (int f = 0; f < F; f++) {
        float w = wr[f];
        vs = fmaf(w, as[hd * F + f], vs);
        vd = fmaf(w, ad[hd * F + f], vd);
    }
    cvec[hd * K + k] = vs;
    cvec[HH * K + hd * K + k] = vd;
}

// ---------------- es/ed directly from x (fp32): es[hd,n] = x[n]·cs[hd] ----------------
template<int K>
__global__ void esedx_k(const float* __restrict__ x, const float* __restrict__ cvec,
                        float2* __restrict__ rowc, float2* __restrict__ evq) {
    int n = blockIdx.x;
    int t = threadIdx.x;  // 128
    __shared__ float xs[K];
    __shared__ float rs[128], rd[128];
    for (int i = t; i < K; i += 128) xs[i] = x[(size_t)n * K + i];
    __syncthreads();
    for (int hd = 0; hd < HH; hd++) {
        float vs = 0.f, vd = 0.f;
        for (int k = t; k < K; k += 128) {
            vs = fmaf(xs[k], cvec[hd * K + k], vs);
            vd = fmaf(xs[k], cvec[HH * K + hd * K + k], vd);
        }
        rs[t] = vs; rd[t] = vd;
        __syncthreads();
#pragma unroll
        for (int s = 64; s > 0; s >>= 1) {
            if (t < s) { rs[t] += rs[t + s]; rd[t] += rd[t + s]; }
            __syncthreads();
        }
        if (t == 0) {
            float es0 = rs[0], ed0 = rd[0];
            rowc[hd * NN + n] = make_float2(expf(es0), expf(0.2f * es0));
            evq [hd * NN + n] = make_float2(expf(ed0), expf(0.2f * ed0));
        }
        __syncthreads();
    }
}

// ---------------- single-plane tf32 GEMM (pre-rounded inputs), double-buffered ----------------
// C = A@B. BM=128,BN=64,BK=32; 8 warps (4m x 2n); 2-stage cp.async pipeline.
__global__ __launch_bounds__(256, 2)
void gemm1t_k(const unsigned* __restrict__ Ag, const unsigned* __restrict__ Bg,
              float* __restrict__ C, int M, int N, int K) {
    constexpr int BM = 128, BN = 64, BK = 32;
    constexpr int AS = BK + 4;
    constexpr int BS = BN + 4;
    constexpr int AW = BM * AS;
    constexpr int BW = BK * BS;
    constexpr int STG = AW + BW;

    extern __shared__ unsigned sm1[];

    int t = threadIdx.x;
    int wid = t >> 5, lane = t & 31;
    int gid = lane >> 2, tid4 = lane & 3;
    int m0 = blockIdx.y * BM, n0 = blockIdx.x * BN;
    int wm = (wid & 3) * 32, wn = (wid >> 2) * 32;

    float acc[2][4][4];
#pragma unroll
    for (int mf = 0; mf < 2; mf++)
#pragma unroll
        for (int nf = 0; nf < 4; nf++)
#pragma unroll
            for (int c = 0; c < 4; c++) acc[mf][nf][c] = 0.f;

    auto load_tile = [&](int st, int k0) {
        unsigned* Ah = sm1 + st * STG;
        unsigned* Bh = Ah + AW;
#pragma unroll
        for (int i = 0; i < (BM * BK) / (256 * 4); i++) {
            int e = (t + i * 256) * 4;
            int m = e / BK, k = e % BK;
            CP_ASYNC16(smem_u32(&Ah[m * AS + k]), Ag + (size_t)(m0 + m) * K + k0 + k);
        }
#pragma unroll
        for (int i = 0; i < (BK * BN) / (256 * 4); i++) {
            int e = (t + i * 256) * 4;
            int k = e / BN, n = e % BN;
            CP_ASYNC16(smem_u32(&Bh[k * BS + n]), Bg + (size_t)(k0 + k) * N + n0 + n);
        }
        CP_COMMIT();
    };

    int NKT = K / BK;
    load_tile(0, 0);

    for (int tt = 0; tt < NKT; tt++) {
        int st = tt & 1;
        if (tt + 1 < NKT) { load_tile(st ^ 1, (tt + 1) * BK); CP_WAIT1(); }
        else             { CP_WAIT0(); }
        __syncthreads();

        const unsigned* Ah = sm1 + st * STG;
        const unsigned* Bh = Ah + AW;

#pragma unroll
        for (int k8 = 0; k8 < BK / 8; k8++) {
            unsigned ah[2][4];
#pragma unroll
            for (int mf = 0; mf < 2; mf++) {
                int r0 = wm + mf * 16 + gid;
                ah[mf][0] = Ah[r0 * AS + k8 * 8 + tid4];
                ah[mf][1] = Ah[(r0 + 8) * AS + k8 * 8 + tid4];
                ah[mf][2] = Ah[r0 * AS + k8 * 8 + tid4 + 4];
                ah[mf][3] = Ah[(r0 + 8) * AS + k8 * 8 + tid4 + 4];
            }
#pragma unroll
            for (int nf = 0; nf < 4; nf++) {
                int cb = wn + nf * 8 + gid;
                unsigned bh0 = Bh[(k8 * 8 + tid4) * BS + cb];
                unsigned bh1 = Bh[(k8 * 8 + tid4 + 4) * BS + cb];
#pragma unroll
                for (int mf = 0; mf < 2; mf++)
                    MMA_TF32(acc[mf][nf], ah[mf][0], ah[mf][1], ah[mf][2], ah[mf][3], bh0, bh1);
            }
        }
        __syncthreads();
    }

#pragma unroll
    for (int mf = 0; mf < 2; mf++) {
        int r0 = m0 + wm + mf * 16 + gid;
#pragma unroll
        for (int nf = 0; nf < 4; nf++) {
            int col = n0 + wn + nf * 8 + tid4 * 2;
            float2 v0 = make_float2(acc[mf][nf][0], acc[mf][nf][1]);
            float2 v1 = make_float2(acc[mf][nf][2], acc[mf][nf][3]);
            *reinterpret_cast<float2*>(&C[(size_t)r0 * N + col]) = v0;
            *reinterpret_cast<float2*>(&C[(size_t)(r0 + 8) * N + col]) = v1;
        }
    }
}

// ---------------- 3xTF32 MMA GEMM on pre-split inputs, double-buffered ----------------
__global__ __launch_bounds__(256, 2)
void gemm3t_pre_k(const unsigned* __restrict__ Agh, const unsigned* __restrict__ Agl,
                  const unsigned* __restrict__ Bgh, const unsigned* __restrict__ Bgl,
                  const float* __restrict__ bias, float* __restrict__ C,
                  int M, int N, int K) {
    constexpr int BM = 128, BN = 64, BK = 32;
    constexpr int AS = BK + 4;
    constexpr int BS = BN + 4;
    constexpr int AW = BM * AS;
    constexpr int BW = BK * BS;
    constexpr int STG = 2 * AW + 2 * BW;

    extern __shared__ unsigned sm[];

    int t = threadIdx.x;
    int wid = t >> 5, lane = t & 31;
    int gid = lane >> 2, tid4 = lane & 3;
    int m0 = blockIdx.y * BM, n0 = blockIdx.x * BN;
    int wm = (wid & 3) * 32, wn = (wid >> 2) * 32;

    float acc[2][4][4];
#pragma unroll
    for (int mf = 0; mf < 2; mf++)
#pragma unroll
        for (int nf = 0; nf < 4; nf++)
#pragma unroll
            for (int c = 0; c < 4; c++) acc[mf][nf][c] = 0.f;

    auto load_tile = [&](int st, int k0) {
        unsigned* Ah = sm + st * STG;
        unsigned* Al = Ah + AW;
        unsigned* Bh = Al + AW;
        unsigned* Bl = Bh + BW;
#pragma unroll
        for (int i = 0; i < (BM * BK) / (256 * 4); i++) {
            int e = (t + i * 256) * 4;
            int m = e / BK, k = e % BK;
            CP_ASYNC16(smem_u32(&Ah[m * AS + k]), Agh + (size_t)(m0 + m) * K + k0 + k);
            CP_ASYNC16(smem_u32(&Al[m * AS + k]), Agl + (size_t)(m0 + m) * K + k0 + k);
        }
#pragma unroll
        for (int i = 0; i < (BK * BN) / (256 * 4); i++) {
            int e = (t + i * 256) * 4;
            int k = e / BN, n = e % BN;
            CP_ASYNC16(smem_u32(&Bh[k * BS + n]), Bgh + (size_t)(k0 + k) * N + n0 + n);
            CP_ASYNC16(smem_u32(&Bl[k * BS + n]), Bgl + (size_t)(k0 + k) * N + n0 + n);
        }
        CP_COMMIT();
    };

    int NKT = K / BK;
    load_tile(0, 0);

    for (int tt = 0; tt < NKT; tt++) {
        int st = tt & 1;
        if (tt + 1 < NKT) { load_tile(st ^ 1, (tt + 1) * BK); CP_WAIT1(); }
        else             { CP_WAIT0(); }
        __syncthreads();

        const unsigned* Ah = sm + st * STG;
        const unsigned* Al = Ah + AW;
        const unsigned* Bh = Al + AW;
        const unsigned* Bl = Bh + BW;

#pragma unroll
        for (int k8 = 0; k8 < BK / 8; k8++) {
            unsigned ah[2][4], al[2][4];
#pragma unroll
            for (int mf = 0; mf < 2; mf++) {
                int r0 = wm + mf * 16 + gid;
                ah[mf][0] = Ah[r0 * AS + k8 * 8 + tid4];
                ah[mf][1] = Ah[(r0 + 8) * AS + k8 * 8 + tid4];
                ah[mf][2] = Ah[r0 * AS + k8 * 8 + tid4 + 4];
                ah[mf][3] = Ah[(r0 + 8) * AS + k8 * 8 + tid4 + 4];
                al[mf][0] = Al[r0 * AS + k8 * 8 + tid4];
                al[mf][1] = Al[(r0 + 8) * AS + k8 * 8 + tid4];
                al[mf][2] = Al[r0 * AS + k8 * 8 + tid4 + 4];
                al[mf][3] = Al[(r0 + 8) * AS + k8 * 8 + tid4 + 4];
            }
#pragma unroll
            for (int nf = 0; nf < 4; nf++) {
                int cb = wn + nf * 8 + gid;
                unsigned bh0 = Bh[(k8 * 8 + tid4) * BS + cb];
                unsigned bh1 = Bh[(k8 * 8 + tid4 + 4) * BS + cb];
                unsigned bl0 = Bl[(k8 * 8 + tid4) * BS + cb];
                unsigned bl1 = Bl[(k8 * 8 + tid4 + 4) * BS + cb];
#pragma unroll
                for (int mf = 0; mf < 2; mf++) {
                    MMA_TF32(acc[mf][nf], ah[mf][0], ah[mf][1], ah[mf][2], ah[mf][3], bh0, bh1);
                    MMA_TF32(acc[mf][nf], ah[mf][0], ah[mf][1], ah[mf][2], ah[mf][3], bl0, bl1);
                    MMA_TF32(acc[mf][nf], al[mf][0], al[mf][1], al[mf][2], al[mf][3], bh0, bh1);
                }
            }
        }
        __syncthreads();
    }

#pragma unroll
    for (int mf = 0; mf < 2; mf++) {
        int r0 = m0 + wm + mf * 16 + gid;
#pragma unroll
        for (int nf = 0; nf < 4; nf++) {
            int col = n0 + wn + nf * 8 + tid4 * 2;
            float b0 = bias ? bias[col] : 0.f;
            float b1 = bias ? bias[col + 1] : 0.f;
            float2 v0 = make_float2(acc[mf][nf][0] + b0, acc[mf][nf][1] + b1);
            float2 v1 = make_float2(acc[mf][nf][2] + b0, acc[mf][nf][3] + b1);
            *reinterpret_cast<float2*>(&C[(size_t)r0 * N + col]) = v0;
            *reinterpret_cast<float2*>(&C[(size_t)(r0 + 8) * N + col]) = v1;
        }
    }
}

// ---------------- generic fp32 tiled GEMM (small cases) ----------------
template<int BM, int BN, int BK, int TM, int TN>
__global__ void gemm_k(const float* __restrict__ A, const float* __restrict__ B,
                       const float* __restrict__ bias, float* __restrict__ C,
                       int M, int N, int K) {
    __shared__ float As[BK][BM];
    __shared__ float Bs[BK][BN];
    constexpr int TX = BN / TN;
    int tid = threadIdx.x;
    int tx = tid % TX, ty = tid / TX;
    int m0 = blockIdx.y * BM, n0 = blockIdx.x * BN;
    float acc[TM][TN];
#pragma unroll
    for (int i = 0; i < TM; i++)
#pragma unroll
        for (int j = 0; j < TN; j++) acc[i][j] = 0.f;

    for (int k0 = 0; k0 < K; k0 += BK) {
#pragma unroll
        for (int idx = tid; idx < BM * BK; idx += 256) {
            int m = idx / BK, k = idx % BK;
            As[k][m] = A[(m0 + m) * K + k0 + k];
        }
#pragma unroll
        for (int idx = tid; idx < BK * BN; idx += 256) {
            int k = idx / BN, n = idx % BN;
            Bs[k][n] = B[(k0 + k) * N + n0 + n];
        }
        __syncthreads();
#pragma unroll
        for (int k = 0; k < BK; k++) {
            float ra[TM], rb[TN];
#pragma unroll
            for (int i = 0; i < TM; i++) ra[i] = As[k][ty * TM + i];
#pragma unroll
            for (int j = 0; j < TN; j++) rb[j] = Bs[k][tx * TN + j];
#pragma unroll
            for (int i = 0; i < TM; i++)
#pragma unroll
                for (int j = 0; j < TN; j++) acc[i][j] = fmaf(ra[i], rb[j], acc[i][j]);
        }
        __syncthreads();
    }
#pragma unroll
    for (int i = 0; i < TM; i++)
#pragma unroll
        for (int j = 0; j < TN; j++) {
            float v = acc[i][j];
            if (bias) v += bias[n0 + tx * TN + j];
            C[(m0 + ty * TM + i) * N + n0 + tx * TN + j] = v;
        }
}

// ---------------- per-node logits from h (layer 2) ----------------
template<int F>
__global__ void esed_k(const float* __restrict__ h, const float* __restrict__ asv,
                       const float* __restrict__ adv, float2* __restrict__ rowc,
                       float2* __restrict__ evq) {
    int n = blockIdx.x;
    int t = threadIdx.x;  // 128
    __shared__ float rs[128], rd[128];
    for (int hd = 0; hd < HH; hd++) {
        float vs = 0.f, vd = 0.f;
        for (int f = t; f < F; f += 128) {
            float hv = h[n * (HH * F) + hd * F + f];
            vs = fmaf(hv, asv[hd * F + f], vs);
            vd = fmaf(hv, adv[hd * F + f], vd);
        }
        rs[t] = vs; rd[t] = vd;
        __syncthreads();
#pragma unroll
        for (int s = 64; s > 0; s >>= 1) {
            if (t < s) { rs[t] += rs[t + s]; rd[t] += rd[t + s]; }
            __syncthreads();
        }
        if (t == 0) {
            float es0 = rs[0], ed0 = rd[0];
            rowc[hd * NN + n] = make_float2(expf(es0), expf(0.2f * es0));
            evq [hd * NN + n] = make_float2(expf(ed0), expf(0.2f * ed0));
        }
        __syncthreads();
    }
}

// ---------------- fused masked-softmax GAT aggregation (tf32 mma) ----------------
template<int F, int FE, int FSPLIT, int JSPLIT>
__global__ __launch_bounds__(128, 4)
void attn_mma_k(const float* __restrict__ h, const float2* __restrict__ rowc,
                const float2* __restrict__ evq, const unsigned* __restrict__ bits,
                float* __restrict__ out, float* __restrict__ pnum,
                float* __restrict__ pden) {
    constexpr int IT = 128;
    constexpr int JT = 64;
    constexpr int HS = FE + 8;
    constexpr int NFRAG = FE / 8;
    constexpr int HF = HH * F;
    constexpr int NV = FE / 4;
    constexpr int JSPAN = NN / JSPLIT;
    constexpr int NT = JSPAN / JT;

    __shared__ float  hs[2][JT * HS];
    __shared__ float2 evq_s[2][JT];
    __shared__ uint2  bits_s[2][IT];
    __shared__ float2 rowc_s[IT];
    __shared__ float  dens[IT];

    int t = threadIdx.x;           // 0..127
    int wid = t >> 5, lane = t & 31;
    int gid = lane >> 2, tid4 = lane & 3;
    int head = blockIdx.y;
    int i0 = blockIdx.x * IT;
    int zz = blockIdx.z;
    int fs = zz % FSPLIT, js = zz / FSPLIT;
    int fofs = fs * FE;
    int jbeg = js * JSPAN;

    int rbase = wid * 32 + gid;

    rowc_s[t] = rowc[head * NN + i0 + t];

    const float* hbase = h + head * F + fofs;
    const unsigned* bbase = bits + (size_t)i0 * (NN / 32);

    auto load_tile = [&](int st, int j0) {
#pragma unroll
        for (int idx = t; idx < JT * NV; idx += 128) {
            int jj = idx / NV, fv = idx % NV;
            CP_ASYNC16(smem_u32(&hs[st][jj * HS + fv * 4]),
                       hbase + (size_t)(j0 + jj) * HF + fv * 4);
        }
        if (t < JT) CP_ASYNC8(smem_u32(&evq_s[st][t]), evq + head * NN + j0 + t);
        CP_ASYNC8(smem_u32(&bits_s[st][t]), bbase + (size_t)t * (NN / 32) + (j0 >> 5));
        CP_COMMIT();
    };

    float acc[2][NFRAG][4];
#pragma unroll
    for (int mf = 0; mf < 2; mf++)
#pragma unroll
        for (int nf = 0; nf < NFRAG; nf++)
#pragma unroll
            for (int c = 0; c < 4; c++) acc[mf][nf][c] = 0.f;
    float dacc[4] = {0.f, 0.f, 0.f, 0.f};

    load_tile(0, jbeg);

    for (int tt = 0; tt < NT; tt++) {
        int st = tt & 1;
        if (tt + 1 < NT) { load_tile(st ^ 1, jbeg + (tt + 1) * JT); CP_WAIT1(); }
        else             { CP_WAIT0(); }
        __syncthreads();

        float2 rc[4];
        uint2  bw[4];
#pragma unroll
        for (int q = 0; q < 4; q++) {
            rc[q] = rowc_s[rbase + q * 8];
            bw[q] = bits_s[st][rbase + q * 8];
        }
        const unsigned* hsu = reinterpret_cast<const unsigned*>(hs[st]);

#pragma unroll
        for (int k = 0; k < JT / 8; k++) {
            int c0 = k * 8 + tid4, c1 = c0 + 4;
            float2 e0 = evq_s[st][c0], e1 = evq_s[st][c1];
            int s0 = c0 & 31, s1 = c1 & 31;

            float w0[4], w1[4];
#pragma unroll
            for (int q = 0; q < 4; q++) {
                unsigned wq = (k < 4) ? bw[q].x : bw[q].y;
                float a = fmaxf(rc[q].x * e0.x, rc[q].y * e0.y);
                if (!((wq >> s0) & 1u)) a = 0.f;
                float b = fmaxf(rc[q].x * e1.x, rc[q].y * e1.y);
                if (!((wq >> s1) & 1u)) b = 0.f;
                w0[q] = a; w1[q] = b;
                dacc[q] += a + b;
            }

            unsigned am0[4] = {__float_as_uint(w0[0]), __float_as_uint(w0[1]),
                               __float_as_uint(w1[0]), __float_as_uint(w1[1])};
            unsigned am1[4] = {__float_as_uint(w0[2]), __float_as_uint(w0[3]),
                               __float_as_uint(w1[2]), __float_as_uint(w1[3])};

#pragma unroll
            for (int nf = 0; nf < NFRAG; nf++) {
                unsigned b0 = hsu[c0 * HS + nf * 8 + gid];
                unsigned b1 = hsu[c1 * HS + nf * 8 + gid];
                MMA_TF32(acc[0][nf], am0[0], am0[1], am0[2], am0[3], b0, b1);
                MMA_TF32(acc[1][nf], am1[0], am1[1], am1[2], am1[3], b0, b1);
            }
        }
        __syncthreads();
    }

#pragma unroll
    for (int q = 0; q < 4; q++) {
        dacc[q] += __shfl_xor_sync(0xffffffffu, dacc[q], 1);
        dacc[q] += __shfl_xor_sync(0xffffffffu, dacc[q], 2);
    }

    if (JSPLIT == 1) {
        if (tid4 == 0) {
#pragma unroll
            for (int q = 0; q < 4; q++) dens[rbase + q * 8] = dacc[q];
        }
        __syncthreads();
        float iv[4];
#pragma unroll
        for (int q = 0; q < 4; q++) iv[q] = 1.f / dens[rbase + q * 8];
#pragma unroll
        for (int mf = 0; mf < 2; mf++)
#pragma unroll
            for (int nf = 0; nf < NFRAG; nf++) {
                int col = head * F + fofs + nf * 8 + tid4 * 2;
                int ra = i0 + rbase + mf * 16;
                float2 v0 = make_float2(acc[mf][nf][0] * iv[mf * 2],
                                        acc[mf][nf][1] * iv[mf * 2]);
                float2 v1 = make_float2(acc[mf][nf][2] * iv[mf * 2 + 1],
                                        acc[mf][nf][3] * iv[mf * 2 + 1]);
                *reinterpret_cast<float2*>(&out[(size_t)ra * HF + col]) = v0;
                *reinterpret_cast<float2*>(&out[(size_t)(ra + 8) * HF + col]) = v1;
            }
    } else {
        if (fs == 0 && tid4 == 0) {
#pragma unroll
            for (int q = 0; q < 4; q++)
                pden[((size_t)js * HH + head) * NN + i0 + rbase + q * 8] = dacc[q];
        }
        float* pb = pnum + (size_t)js * NN * HF;
#pragma unroll
        for (int mf = 0; mf < 2; mf++)
#pragma unroll
            for (int nf = 0; nf < NFRAG; nf++) {
                int col = head * F + fofs + nf * 8 + tid4 * 2;
                int ra = i0 + rbase + mf * 16;
                float2 v0 = make_float2(acc[mf][nf][0], acc[mf][nf][1]);
                float2 v1 = make_float2(acc[mf][nf][2], acc[mf][nf][3]);
                *reinterpret_cast<float2*>(&pb[(size_t)ra * HF + col]) = v0;
                *reinterpret_cast<float2*>(&pb[(size_t)(ra + 8) * HF + col]) = v1;
            }
    }
}

// combine j-split partials: v = sum(pnum)/sum(pden).
template<int F, int JS, bool SPLITOUT>
__global__ void combine_k(const float* __restrict__ p, const float* __restrict__ dp,
                          float* __restrict__ out, unsigned* __restrict__ ohi,
                          unsigned* __restrict__ olo) {
    constexpr int HF = HH * F;
    int n = blockIdx.x;
    for (int c = threadIdx.x; c < HF; c += blockDim.x) {
        int head = c / F;
        float d = 0.f, v = 0.f;
#pragma unroll
        for (int z = 0; z < JS; z++) {
            d += dp[((size_t)z * HH + head) * NN + n];
            v += p[(size_t)z * NN * HF + (size_t)n * HF + c];
        }
        v /= d;
        if (SPLITOUT) {
            unsigned h, l;
            split_tf32(v, h, l);
            ohi[(size_t)n * HF + c] = h;
            olo[(size_t)n * HF + c] = l;
        } else {
            out[(size_t)n * HF + c] = v;
        }
    }
}

// ---------------- batchnorm stats ----------------
template<int C>
__global__ void bnstats_k(const float* __restrict__ y, float* __restrict__ stats) {
    int c = blockIdx.x;
    int t = threadIdx.x;  // 256
    float s = 0.f, q = 0.f;
    for (int r = t; r < NN; r += 256) {
        float v = y[r * C + c];
        s += v; q = fmaf(v, v, q);
    }
    __shared__ float ss[256], qq[256];
    ss[t] = s; qq[t] = q;
    __syncthreads();
#pragma unroll
    for (int o = 128; o > 0; o >>= 1) {
        if (t < o) { ss[t] += ss[t + o]; qq[t] += qq[t + o]; }
        __syncthreads();
    }
    if (t == 0) {
        float mean = ss[0] / (float)NN;
        float var  = qq[0] / (float)NN - mean * mean;
        stats[c]       = mean;
        stats[128 + c] = rsqrtf(var + 1e-5f);
    }
}

// ---------------- normalize + affine + ELU ----------------
template<int C>
__global__ void bnelu_k(const float* __restrict__ y, const float* __restrict__ stats,
                        const float* __restrict__ g, const float* __restrict__ b,
                        float* __restrict__ out) {
    int idx = blockIdx.x * blockDim.x + threadIdx.x;
    if (idx >= NN * C) return;
    int c = idx % C;
    float v = (y[idx] - stats[c]) * stats[128 + c];
    v = fmaf(v, g[c], b[c]);
    out[idx] = v > 0.f ? v : expm1f(v);
}

// ---------------- launch ----------------
extern "C" void kernel_launch(void* const* d_in, const int* in_sizes, int n_in,
                              void* d_out, int out_size) {
    const float* x   = (const float*)d_in[0];
    const int*   adj = (const int*)d_in[1];
    const float* W1  = (const float*)d_in[2];
    const float* a1s = (const float*)d_in[3];
    const float* a1d = (const float*)d_in[4];
    const float* lw1 = (const float*)d_in[5];
    const float* lb1 = (const float*)d_in[6];
    const float* g1  = (const float*)d_in[7];
    const float* be1 = (const float*)d_in[8];
    const float* W2  = (const float*)d_in[9];
    const float* a2s = (const float*)d_in[10];
    const float* a2d = (const float*)d_in[11];
    const float* lw2 = (const float*)d_in[12];
    const float* lb2 = (const float*)d_in[13];
    const float* g2  = (const float*)d_in[14];
    const float* be2 = (const float*)d_in[15];
    float* out = (float*)d_out;

    float *h1, *y1, *x2, *h2, *x3, *y2, *stats, *part, *dpart, *cvec;
    float2 *rowc1, *evq1, *rowc2, *evq2;
    unsigned *bitsp, *spAh, *spAl, *spBh, *spBl;
    cudaGetSymbolAddress((void**)&h1,  g_h1);
    cudaGetSymbolAddress((void**)&y1,  g_y1);
    cudaGetSymbolAddress((void**)&x2,  g_x2);
    cudaGetSymbolAddress((void**)&h2,  g_h2);
    cudaGetSymbolAddress((void**)&x3,  g_x3);
    cudaGetSymbolAddress((void**)&y2,  g_y2);
    cudaGetSymbolAddress((void**)&rowc1, g_rowc1);
    cudaGetSymbolAddress((void**)&evq1,  g_evq1);
    cudaGetSymbolAddress((void**)&rowc2, g_rowc2);
    cudaGetSymbolAddress((void**)&evq2,  g_evq2);
    cudaGetSymbolAddress((void**)&stats, g_stats);
    cudaGetSymbolAddress((void**)&part,  g_part);
    cudaGetSymbolAddress((void**)&dpart, g_dpart);
    cudaGetSymbolAddress((void**)&bitsp, g_adjbits);
    cudaGetSymbolAddress((void**)&spAh, g_spAh);
    cudaGetSymbolAddress((void**)&spAl, g_spAl);
    cudaGetSymbolAddress((void**)&spBh, g_spBh);
    cudaGetSymbolAddress((void**)&spBl, g_spBl);
    cudaGetSymbolAddress((void**)&cvec, g_cvec);

    const int gemm3_smem = 2 * (2 * 128 * 36 + 2 * 32 * 68) * 4;   // 108544 B
    const int gemm1_smem = 2 * (128 * 36 + 32 * 68) * 4;           // 54272 B
    cudaFuncSetAttribute(gemm3t_pre_k, cudaFuncAttributeMaxDynamicSharedMemorySize, gemm3_smem);
    cudaFuncSetAttribute(gemm1t_k, cudaFuncAttributeMaxDynamicSharedMemorySize, gemm1_smem);

    // pack adjacency to bits
    pack_adj_k<<<(NN * NN) / 256, 256>>>(adj, bitsp);

    // ---- layer 1 GAT ----
    // es/ed directly from x (fp32): fold W1 through attention vectors
    cvec_k<<<(512 * HH + 255) / 256, 256>>>(W1, a1s, a1d, cvec, 512, 128);
    esedx_k<512><<<NN, 128>>>(x, cvec, rowc1, evq1);
    // h1 = x@W1 single-plane tf32 (rna-prerounded inputs)
    preround_k<<<(NN * 512) / 256, 256>>>(x, spAh, NN * 512);
    preround_k<<<(512 * 512) / 256, 256>>>(W1, spBh, 512 * 512);
    gemm1t_k<<<dim3(512 / 64, NN / 128), 256, gemm1_smem>>>(spAh, spBh, h1, NN, 512, 512);
    // F=128: FSPLIT=2 x JSPLIT=2 -> grid 32x4x4 = 512 blocks of 128 thr
    attn_mma_k<128, 64, 2, 2><<<dim3(NN / 128, HH, 4), 128>>>(h1, rowc1, evq1, bitsp, nullptr, part, dpart);
    // combine writes tf32 hi/lo planes of x1 directly (consumed only by lw1 GEMM)
    combine_k<128, 2, true><<<NN, 256>>>(part, dpart, nullptr, spAh, spAl);

    // ---- MLP 1 + BN + ELU ----
    presplit_k<<<(512 * 64) / 256, 256>>>(lw1, spBh, spBl, 512 * 64);
    gemm3t_pre_k<<<dim3(1, NN / 128), 256, gemm3_smem>>>(spAh, spAl, spBh, spBl, lb1, y1, NN, 64, 512);
    bnstats_k<64><<<64, 256>>>(y1, stats);
    bnelu_k<64><<<(NN * 64) / 256, 256>>>(y1, stats, g1, be1, x2);

    // ---- layer 2 GAT ----
    gemm_k<128, 64, 16, 8, 4><<<dim3(2, NN / 128), 256>>>(x2, W2, nullptr, h2, NN, 128, 64);
    esed_k<32><<<NN, 128>>>(h2, a2s, a2d, rowc2, evq2);
    // F=FE=32: JSPLIT=4 -> grid 32x4x4 = 512 blocks of 128 thr
    attn_mma_k<32, 32, 1, 4><<<dim3(NN / 128, HH, 4), 128>>>(h2, rowc2, evq2, bitsp, nullptr, part, dpart);
    combine_k<32, 4, false><<<NN, 128>>>(part, dpart, x3, nullptr, nullptr);

    // ---- MLP 2 + BN + ELU ----
    gemm_k<64, 16, 16, 4, 1><<<dim3(1, NN / 64), 256>>>(x3, lw2, lb2, y2, NN, 16, 128);
    bnstats_k<16><<<16, 256>>>(y2, stats);
    bnelu_k<16><<<(NN * 16) / 256, 256>>>(y2, stats, g2, be2, out);
}

// round 15
// speedup vs baseline: 1.1227x; 1.0540x over previous
#include <cuda_runtime.h>
#include <cuda_bf16.h>
#include <cstdint>

#define NN 4096
#define HH 4

// ---------------- scratch ----------------
__device__ float  g_h1 [NN * 512];
__device__ float  g_y1 [NN * 64];
__device__ float  g_x2 [NN * 64];
__device__ float  g_h2 [NN * 128];
__device__ float  g_x3 [NN * 128];
__device__ float  g_y2 [NN * 16];
__device__ float2 g_rowc1[HH * NN];   // {e^es, e^{0.2es}}
__device__ float2 g_evq1 [HH * NN];   // {e^ed, e^{0.2ed}}
__device__ float2 g_rowc2[HH * NN];
__device__ float2 g_evq2 [HH * NN];
__device__ unsigned g_adjbits[NN * (NN / 32)];
__device__ float  g_part [2 * NN * 512];   // attn partial numerators
__device__ float  g_dpart[4 * HH * NN];    // partial denominators
__device__ unsigned g_spAh[NN * 512], g_spAl[NN * 512];   // tf32 planes (x / x1 hi,lo)
__device__ unsigned g_spBh[512 * 512], g_spBl[512 * 512]; // tf32 planes (W1 / lw1)
__device__ float  g_cvec[2 * HH * 512];    // cs1 | cd1  (W1-folded attention vectors)

// ---------------- helpers ----------------
__device__ __forceinline__ unsigned smem_u32(const void* p) {
    return (unsigned)__cvta_generic_to_shared(p);
}
#define CP_ASYNC16(dst, src) \
    asm volatile("cp.async.cg.shared.global [%0], [%1], 16;" :: "r"(dst), "l"(src))
#define CP_ASYNC8(dst, src) \
    asm volatile("cp.async.ca.shared.global [%0], [%1], 8;" :: "r"(dst), "l"(src))
#define CP_COMMIT() asm volatile("cp.async.commit_group;")
#define CP_WAIT1()  asm volatile("cp.async.wait_group 1;")
#define CP_WAIT0()  asm volatile("cp.async.wait_group 0;")

#define MMA_TF32(acc, a0, a1, a2, a3, b0, b1)                                   \
    asm volatile(                                                               \
        "mma.sync.aligned.m16n8k8.row.col.f32.tf32.tf32.f32 "                   \
        "{%0,%1,%2,%3}, {%4,%5,%6,%7}, {%8,%9}, {%0,%1,%2,%3};"                 \
        : "+f"(acc[0]), "+f"(acc[1]), "+f"(acc[2]), "+f"(acc[3])                \
        : "r"(a0), "r"(a1), "r"(a2), "r"(a3), "r"(b0), "r"(b1))

__device__ __forceinline__ void split_tf32(float v, unsigned& h, unsigned& l) {
    unsigned hv;
    asm("cvt.rna.tf32.f32 %0, %1;" : "=r"(hv) : "f"(v));
    float lo = v - __uint_as_float(hv);
    unsigned lv;
    asm("cvt.rna.tf32.f32 %0, %1;" : "=r"(lv) : "f"(lo));
    h = hv; l = lv;
}

// ---------------- adjacency packing: 1 thread = 1 mask word (32 ints via 8 x int4)
__global__ void pack_adj_k(const int4* __restrict__ adj4, unsigned* __restrict__ bits) {
    int w = blockIdx.x * blockDim.x + threadIdx.x;   // word index, NN*NN/32 total
    const int4* p = adj4 + (size_t)w * 8;
    unsigned word = 0;
#pragma unroll
    for (int i = 0; i < 8; i++) {
        int4 v = p[i];
        word |= (v.x > 0 ? 1u : 0u) << (4 * i);
        word |= (v.y > 0 ? 1u : 0u) << (4 * i + 1);
        word |= (v.z > 0 ? 1u : 0u) << (4 * i + 2);
        word |= (v.w > 0 ? 1u : 0u) << (4 * i + 3);
    }
    bits[w] = word;
}

// ---------------- tf32 rna pre-round (single plane, unbiased) ----------------
__global__ void preround_k(const float* __restrict__ a, unsigned* __restrict__ hi, int n) {
    int i = blockIdx.x * blockDim.x + threadIdx.x;
    if (i >= n) return;
    unsigned h;
    asm("cvt.rna.tf32.f32 %0, %1;" : "=r"(h) : "f"(a[i]));
    hi[i] = h;
}

// ---------------- tf32 hi/lo pre-split (elementwise) ----------------
__global__ void presplit_k(const float* __restrict__ a, unsigned* __restrict__ hi,
                           unsigned* __restrict__ lo, int n) {
    int i = blockIdx.x * blockDim.x + threadIdx.x;
    if (i >= n) return;
    unsigned h, l;
    split_tf32(a[i], h, l);
    hi[i] = h; lo[i] = l;
}

// ---------------- fold attention vectors through W1 ----------------
__global__ void cvec_k(const float* __restrict__ W, const float* __restrict__ as,
                       const float* __restrict__ ad, float* __restrict__ cvec,
                       int K, int F) {
    int idx = blockIdx.x * blockDim.x + threadIdx.x;   // over K*HH
    if (idx >= K * HH) return;
    int k = idx / HH, hd = idx % HH;
    float vs = 0.f, vd = 0.f;
    const float* wr = W + (size_t)k * (HH * F) + hd * F;
    for (int f = 0; f < F; f++) {
        float w = wr[f];
        vs = fmaf(w, as[hd * F + f], vs);
        vd = fmaf(w, ad[hd * F + f], vd);
    }
    cvec[hd * K + k] = vs;
    cvec[HH * K + hd * K + k] = vd;
}

// ---------------- es/ed directly from x (fp32) + rna-rounded x plane ----------------
template<int K>
__global__ void esedx_k(const float* __restrict__ x, const float* __restrict__ cvec,
                        float2* __restrict__ rowc, float2* __restrict__ evq,
                        unsigned* __restrict__ xr) {
    int n = blockIdx.x;
    int t = threadIdx.x;  // 128
    __shared__ float xs[K];
    __shared__ float rs[128], rd[128];
    for (int i = t; i < K; i += 128) {
        float v = x[(size_t)n * K + i];
        xs[i] = v;
        unsigned h;
        asm("cvt.rna.tf32.f32 %0, %1;" : "=r"(h) : "f"(v));
        xr[(size_t)n * K + i] = h;
    }
    __syncthreads();
    for (int hd = 0; hd < HH; hd++) {
        float vs = 0.f, vd = 0.f;
        for (int k = t; k < K; k += 128) {
            vs = fmaf(xs[k], cvec[hd * K + k], vs);
            vd = fmaf(xs[k], cvec[HH * K + hd * K + k], vd);
        }
        rs[t] = vs; rd[t] = vd;
        __syncthreads();
#pragma unroll
        for (int s = 64; s > 0; s >>= 1) {
            if (t < s) { rs[t] += rs[t + s]; rd[t] += rd[t + s]; }
            __syncthreads();
        }
        if (t == 0) {
            float es0 = rs[0], ed0 = rd[0];
            rowc[hd * NN + n] = make_float2(expf(es0), expf(0.2f * es0));
            evq [hd * NN + n] = make_float2(expf(ed0), expf(0.2f * ed0));
        }
        __syncthreads();
    }
}

// ---------------- single-plane tf32 GEMM (pre-rounded inputs), double-buffered ----------------
__global__ __launch_bounds__(256, 2)
void gemm1t_k(const unsigned* __restrict__ Ag, const unsigned* __restrict__ Bg,
              float* __restrict__ C, int M, int N, int K) {
    constexpr int BM = 128, BN = 64, BK = 32;
    constexpr int AS = BK + 4;
    constexpr int BS = BN + 4;
    constexpr int AW = BM * AS;
    constexpr int BW = BK * BS;
    constexpr int STG = AW + BW;

    extern __shared__ unsigned sm1[];

    int t = threadIdx.x;
    int wid = t >> 5, lane = t & 31;
    int gid = lane >> 2, tid4 = lane & 3;
    int m0 = blockIdx.y * BM, n0 = blockIdx.x * BN;
    int wm = (wid & 3) * 32, wn = (wid >> 2) * 32;

    float acc[2][4][4];
#pragma unroll
    for (int mf = 0; mf < 2; mf++)
#pragma unroll
        for (int nf = 0; nf < 4; nf++)
#pragma unroll
            for (int c = 0; c < 4; c++) acc[mf][nf][c] = 0.f;

    auto load_tile = [&](int st, int k0) {
        unsigned* Ah = sm1 + st * STG;
        unsigned* Bh = Ah + AW;
#pragma unroll
        for (int i = 0; i < (BM * BK) / (256 * 4); i++) {
            int e = (t + i * 256) * 4;
            int m = e / BK, k = e % BK;
            CP_ASYNC16(smem_u32(&Ah[m * AS + k]), Ag + (size_t)(m0 + m) * K + k0 + k);
        }
#pragma unroll
        for (int i = 0; i < (BK * BN) / (256 * 4); i++) {
            int e = (t + i * 256) * 4;
            int k = e / BN, n = e % BN;
            CP_ASYNC16(smem_u32(&Bh[k * BS + n]), Bg + (size_t)(k0 + k) * N + n0 + n);
        }
        CP_COMMIT();
    };

    int NKT = K / BK;
    load_tile(0, 0);

    for (int tt = 0; tt < NKT; tt++) {
        int st = tt & 1;
        if (tt + 1 < NKT) { load_tile(st ^ 1, (tt + 1) * BK); CP_WAIT1(); }
        else             { CP_WAIT0(); }
        __syncthreads();

        const unsigned* Ah = sm1 + st * STG;
        const unsigned* Bh = Ah + AW;

#pragma unroll
        for (int k8 = 0; k8 < BK / 8; k8++) {
            unsigned ah[2][4];
#pragma unroll
            for (int mf = 0; mf < 2; mf++) {
                int r0 = wm + mf * 16 + gid;
                ah[mf][0] = Ah[r0 * AS + k8 * 8 + tid4];
                ah[mf][1] = Ah[(r0 + 8) * AS + k8 * 8 + tid4];
                ah[mf][2] = Ah[r0 * AS + k8 * 8 + tid4 + 4];
                ah[mf][3] = Ah[(r0 + 8) * AS + k8 * 8 + tid4 + 4];
            }
#pragma unroll
            for (int nf = 0; nf < 4; nf++) {
                int cb = wn + nf * 8 + gid;
                unsigned bh0 = Bh[(k8 * 8 + tid4) * BS + cb];
                unsigned bh1 = Bh[(k8 * 8 + tid4 + 4) * BS + cb];
#pragma unroll
                for (int mf = 0; mf < 2; mf++)
                    MMA_TF32(acc[mf][nf], ah[mf][0], ah[mf][1], ah[mf][2], ah[mf][3], bh0, bh1);
            }
        }
        __syncthreads();
    }

#pragma unroll
    for (int mf = 0; mf < 2; mf++) {
        int r0 = m0 + wm + mf * 16 + gid;
#pragma unroll
        for (int nf = 0; nf < 4; nf++) {
            int col = n0 + wn + nf * 8 + tid4 * 2;
            float2 v0 = make_float2(acc[mf][nf][0], acc[mf][nf][1]);
            float2 v1 = make_float2(acc[mf][nf][2], acc[mf][nf][3]);
            *reinterpret_cast<float2*>(&C[(size_t)r0 * N + col]) = v0;
            *reinterpret_cast<float2*>(&C[(size_t)(r0 + 8) * N + col]) = v1;
        }
    }
}

// ---------------- 3xTF32 MMA GEMM on pre-split inputs, double-buffered ----------------
__global__ __launch_bounds__(256, 2)
void gemm3t_pre_k(const unsigned* __restrict__ Agh, const unsigned* __restrict__ Agl,
                  const unsigned* __restrict__ Bgh, const unsigned* __restrict__ Bgl,
                  const float* __restrict__ bias, float* __restrict__ C,
                  int M, int N, int K) {
    constexpr int BM = 128, BN = 64, BK = 32;
    constexpr int AS = BK + 4;
    constexpr int BS = BN + 4;
    constexpr int AW = BM * AS;
    constexpr int BW = BK * BS;
    constexpr int STG = 2 * AW + 2 * BW;

    extern __shared__ unsigned sm[];

    int t = threadIdx.x;
    int wid = t >> 5, lane = t & 31;
    int gid = lane >> 2, tid4 = lane & 3;
    int m0 = blockIdx.y * BM, n0 = blockIdx.x * BN;
    int wm = (wid & 3) * 32, wn = (wid >> 2) * 32;

    float acc[2][4][4];
#pragma unroll
    for (int mf = 0; mf < 2; mf++)
#pragma unroll
        for (int nf = 0; nf < 4; nf++)
#pragma unroll
            for (int c = 0; c < 4; c++) acc[mf][nf][c] = 0.f;

    auto load_tile = [&](int st, int k0) {
        unsigned* Ah = sm + st * STG;
        unsigned* Al = Ah + AW;
        unsigned* Bh = Al + AW;
        unsigned* Bl = Bh + BW;
#pragma unroll
        for (int i = 0; i < (BM * BK) / (256 * 4); i++) {
            int e = (t + i * 256) * 4;
            int m = e / BK, k = e % BK;
            CP_ASYNC16(smem_u32(&Ah[m * AS + k]), Agh + (size_t)(m0 + m) * K + k0 + k);
            CP_ASYNC16(smem_u32(&Al[m * AS + k]), Agl + (size_t)(m0 + m) * K + k0 + k);
        }
#pragma unroll
        for (int i = 0; i < (BK * BN) / (256 * 4); i++) {
            int e = (t + i * 256) * 4;
            int k = e / BN, n = e % BN;
            CP_ASYNC16(smem_u32(&Bh[k * BS + n]), Bgh + (size_t)(k0 + k) * N + n0 + n);
            CP_ASYNC16(smem_u32(&Bl[k * BS + n]), Bgl + (size_t)(k0 + k) * N + n0 + n);
        }
        CP_COMMIT();
    };

    int NKT = K / BK;
    load_tile(0, 0);

    for (int tt = 0; tt < NKT; tt++) {
        int st = tt & 1;
        if (tt + 1 < NKT) { load_tile(st ^ 1, (tt + 1) * BK); CP_WAIT1(); }
        else             { CP_WAIT0(); }
        __syncthreads();

        const unsigned* Ah = sm + st * STG;
        const unsigned* Al = Ah + AW;
        const unsigned* Bh = Al + AW;
        const unsigned* Bl = Bh + BW;

#pragma unroll
        for (int k8 = 0; k8 < BK / 8; k8++) {
            unsigned ah[2][4], al[2][4];
#pragma unroll
            for (int mf = 0; mf < 2; mf++) {
                int r0 = wm + mf * 16 + gid;
                ah[mf][0] = Ah[r0 * AS + k8 * 8 + tid4];
                ah[mf][1] = Ah[(r0 + 8) * AS + k8 * 8 + tid4];
                ah[mf][2] = Ah[r0 * AS + k8 * 8 + tid4 + 4];
                ah[mf][3] = Ah[(r0 + 8) * AS + k8 * 8 + tid4 + 4];
                al[mf][0] = Al[r0 * AS + k8 * 8 + tid4];
                al[mf][1] = Al[(r0 + 8) * AS + k8 * 8 + tid4];
                al[mf][2] = Al[r0 * AS + k8 * 8 + tid4 + 4];
                al[mf][3] = Al[(r0 + 8) * AS + k8 * 8 + tid4 + 4];
            }
#pragma unroll
            for (int nf = 0; nf < 4; nf++) {
                int cb = wn + nf * 8 + gid;
                unsigned bh0 = Bh[(k8 * 8 + tid4) * BS + cb];
                unsigned bh1 = Bh[(k8 * 8 + tid4 + 4) * BS + cb];
                unsigned bl0 = Bl[(k8 * 8 + tid4) * BS + cb];
                unsigned bl1 = Bl[(k8 * 8 + tid4 + 4) * BS + cb];
#pragma unroll
                for (int mf = 0; mf < 2; mf++) {
                    MMA_TF32(acc[mf][nf], ah[mf][0], ah[mf][1], ah[mf][2], ah[mf][3], bh0, bh1);
                    MMA_TF32(acc[mf][nf], ah[mf][0], ah[mf][1], ah[mf][2], ah[mf][3], bl0, bl1);
                    MMA_TF32(acc[mf][nf], al[mf][0], al[mf][1], al[mf][2], al[mf][3], bh0, bh1);
                }
            }
        }
        __syncthreads();
    }

#pragma unroll
    for (int mf = 0; mf < 2; mf++) {
        int r0 = m0 + wm + mf * 16 + gid;
#pragma unroll
        for (int nf = 0; nf < 4; nf++) {
            int col = n0 + wn + nf * 8 + tid4 * 2;
            float b0 = bias ? bias[col] : 0.f;
            float b1 = bias ? bias[col + 1] : 0.f;
            float2 v0 = make_float2(acc[mf][nf][0] + b0, acc[mf][nf][1] + b1);
            float2 v1 = make_float2(acc[mf][nf][2] + b0, acc[mf][nf][3] + b1);
            *reinterpret_cast<float2*>(&C[(size_t)r0 * N + col]) = v0;
            *reinterpret_cast<float2*>(&C[(size_t)(r0 + 8) * N + col]) = v1;
        }
    }
}

// ---------------- generic fp32 tiled GEMM (small cases) ----------------
template<int BM, int BN, int BK, int TM, int TN>
__global__ void gemm_k(const float* __restrict__ A, const float* __restrict__ B,
                       const float* __restrict__ bias, float* __restrict__ C,
                       int M, int N, int K) {
    __shared__ float As[BK][BM];
    __shared__ float Bs[BK][BN];
    constexpr int TX = BN / TN;
    int tid = threadIdx.x;
    int tx = tid % TX, ty = tid / TX;
    int m0 = blockIdx.y * BM, n0 = blockIdx.x * BN;
    float acc[TM][TN];
#pragma unroll
    for (int i = 0; i < TM; i++)
#pragma unroll
        for (int j = 0; j < TN; j++) acc[i][j] = 0.f;

    for (int k0 = 0; k0 < K; k0 += BK) {
#pragma unroll
        for (int idx = tid; idx < BM * BK; idx += 256) {
            int m = idx / BK, k = idx % BK;
            As[k][m] = A[(m0 + m) * K + k0 + k];
        }
#pragma unroll
        for (int idx = tid; idx < BK * BN; idx += 256) {
            int k = idx / BN, n = idx % BN;
            Bs[k][n] = B[(k0 + k) * N + n0 + n];
        }
        __syncthreads();
#pragma unroll
        for (int k = 0; k < BK; k++) {
            float ra[TM], rb[TN];
#pragma unroll
            for (int i = 0; i < TM; i++) ra[i] = As[k][ty * TM + i];
#pragma unroll
            for (int j = 0; j < TN; j++) rb[j] = Bs[k][tx * TN + j];
#pragma unroll
            for (int i = 0; i < TM; i++)
#pragma unroll
                for (int j = 0; j < TN; j++) acc[i][j] = fmaf(ra[i], rb[j], acc[i][j]);
        }
        __syncthreads();
    }
#pragma unroll
    for (int i = 0; i < TM; i++)
#pragma unroll
        for (int j = 0; j < TN; j++) {
            float v = acc[i][j];
            if (bias) v += bias[n0 + tx * TN + j];
            C[(m0 + ty * TM + i) * N + n0 + tx * TN + j] = v;
        }
}

// ---------------- per-node logits from h (layer 2) ----------------
template<int F>
__global__ void esed_k(const float* __restrict__ h, const float* __restrict__ asv,
                       const float* __restrict__ adv, float2* __restrict__ rowc,
                       float2* __restrict__ evq) {
    int n = blockIdx.x;
    int t = threadIdx.x;  // 128
    __shared__ float rs[128], rd[128];
    for (int hd = 0; hd < HH; hd++) {
        float vs = 0.f, vd = 0.f;
        for (int f = t; f < F; f += 128) {
            float hv = h[n * (HH * F) + hd * F + f];
            vs = fmaf(hv, asv[hd * F + f], vs);
            vd = fmaf(hv, adv[hd * F + f], vd);
        }
        rs[t] = vs; rd[t] = vd;
        __syncthreads();
#pragma unroll
        for (int s = 64; s > 0; s >>= 1) {
            if (t < s) { rs[t] += rs[t + s]; rd[t] += rd[t + s]; }
            __syncthreads();
        }
        if (t == 0) {
            float es0 = rs[0], ed0 = rd[0];
            rowc[hd * NN + n] = make_float2(expf(es0), expf(0.2f * es0));
            evq [hd * NN + n] = make_float2(expf(ed0), expf(0.2f * ed0));
        }
        __syncthreads();
    }
}

// ---------------- fused masked-softmax GAT aggregation (tf32 mma) ----------------
template<int F, int FE, int FSPLIT, int JSPLIT>
__global__ __launch_bounds__(128, 4)
void attn_mma_k(const float* __restrict__ h, const float2* __restrict__ rowc,
                const float2* __restrict__ evq, const unsigned* __restrict__ bits,
                float* __restrict__ out, float* __restrict__ pnum,
                float* __restrict__ pden) {
    constexpr int IT = 128;
    constexpr int JT = 64;
    constexpr int HS = FE + 8;
    constexpr int NFRAG = FE / 8;
    constexpr int HF = HH * F;
    constexpr int NV = FE / 4;
    constexpr int JSPAN = NN / JSPLIT;
    constexpr int NT = JSPAN / JT;

    __shared__ float  hs[2][JT * HS];
    __shared__ float2 evq_s[2][JT];
    __shared__ uint2  bits_s[2][IT];
    __shared__ float2 rowc_s[IT];
    __shared__ float  dens[IT];

    int t = threadIdx.x;           // 0..127
    int wid = t >> 5, lane = t & 31;
    int gid = lane >> 2, tid4 = lane & 3;
    int head = blockIdx.y;
    int i0 = blockIdx.x * IT;
    int zz = blockIdx.z;
    int fs = zz % FSPLIT, js = zz / FSPLIT;
    int fofs = fs * FE;
    int jbeg = js * JSPAN;

    int rbase = wid * 32 + gid;

    rowc_s[t] = rowc[head * NN + i0 + t];

    const float* hbase = h + head * F + fofs;
    const unsigned* bbase = bits + (size_t)i0 * (NN / 32);

    auto load_tile = [&](int st, int j0) {
#pragma unroll
        for (int idx = t; idx < JT * NV; idx += 128) {
            int jj = idx / NV, fv = idx % NV;
            CP_ASYNC16(smem_u32(&hs[st][jj * HS + fv * 4]),
                       hbase + (size_t)(j0 + jj) * HF + fv * 4);
        }
        if (t < JT) CP_ASYNC8(smem_u32(&evq_s[st][t]), evq + head * NN + j0 + t);
        CP_ASYNC8(smem_u32(&bits_s[st][t]), bbase + (size_t)t * (NN / 32) + (j0 >> 5));
        CP_COMMIT();
    };

    float acc[2][NFRAG][4];
#pragma unroll
    for (int mf = 0; mf < 2; mf++)
#pragma unroll
        for (int nf = 0; nf < NFRAG; nf++)
#pragma unroll
            for (int c = 0; c < 4; c++) acc[mf][nf][c] = 0.f;
    float dacc[4] = {0.f, 0.f, 0.f, 0.f};

    load_tile(0, jbeg);

    for (int tt = 0; tt < NT; tt++) {
        int st = tt & 1;
        if (tt + 1 < NT) { load_tile(st ^ 1, jbeg + (tt + 1) * JT); CP_WAIT1(); }
        else             { CP_WAIT0(); }
        __syncthreads();

        float2 rc[4];
        uint2  bw[4];
#pragma unroll
        for (int q = 0; q < 4; q++) {
            rc[q] = rowc_s[rbase + q * 8];
            bw[q] = bits_s[st][rbase + q * 8];
        }
        const unsigned* hsu = reinterpret_cast<const unsigned*>(hs[st]);

#pragma unroll
        for (int k = 0; k < JT / 8; k++) {
            int c0 = k * 8 + tid4, c1 = c0 + 4;
            float2 e0 = evq_s[st][c0], e1 = evq_s[st][c1];
            int s0 = c0 & 31, s1 = c1 & 31;

            float w0[4], w1[4];
#pragma unroll
            for (int q = 0; q < 4; q++) {
                unsigned wq = (k < 4) ? bw[q].x : bw[q].y;
                float a = fmaxf(rc[q].x * e0.x, rc[q].y * e0.y);
                if (!((wq >> s0) & 1u)) a = 0.f;
                float b = fmaxf(rc[q].x * e1.x, rc[q].y * e1.y);
                if (!((wq >> s1) & 1u)) b = 0.f;
                w0[q] = a; w1[q] = b;
                dacc[q] += a + b;
            }

            unsigned am0[4] = {__float_as_uint(w0[0]), __float_as_uint(w0[1]),
                               __float_as_uint(w1[0]), __float_as_uint(w1[1])};
            unsigned am1[4] = {__float_as_uint(w0[2]), __float_as_uint(w0[3]),
                               __float_as_uint(w1[2]), __float_as_uint(w1[3])};

#pragma unroll
            for (int nf = 0; nf < NFRAG; nf++) {
                unsigned b0 = hsu[c0 * HS + nf * 8 + gid];
                unsigned b1 = hsu[c1 * HS + nf * 8 + gid];
                MMA_TF32(acc[0][nf], am0[0], am0[1], am0[2], am0[3], b0, b1);
                MMA_TF32(acc[1][nf], am1[0], am1[1], am1[2], am1[3], b0, b1);
            }
        }
        __syncthreads();
    }

#pragma unroll
    for (int q = 0; q < 4; q++) {
        dacc[q] += __shfl_xor_sync(0xffffffffu, dacc[q], 1);
        dacc[q] += __shfl_xor_sync(0xffffffffu, dacc[q], 2);
    }

    if (JSPLIT == 1) {
        if (tid4 == 0) {
#pragma unroll
            for (int q = 0; q < 4; q++) dens[rbase + q * 8] = dacc[q];
        }
        __syncthreads();
        float iv[4];
#pragma unroll
        for (int q = 0; q < 4; q++) iv[q] = 1.f / dens[rbase + q * 8];
#pragma unroll
        for (int mf = 0; mf < 2; mf++)
#pragma unroll
            for (int nf = 0; nf < NFRAG; nf++) {
                int col = head * F + fofs + nf * 8 + tid4 * 2;
                int ra = i0 + rbase + mf * 16;
                float2 v0 = make_float2(acc[mf][nf][0] * iv[mf * 2],
                                        acc[mf][nf][1] * iv[mf * 2]);
                float2 v1 = make_float2(acc[mf][nf][2] * iv[mf * 2 + 1],
                                        acc[mf][nf][3] * iv[mf * 2 + 1]);
                *reinterpret_cast<float2*>(&out[(size_t)ra * HF + col]) = v0;
                *reinterpret_cast<float2*>(&out[(size_t)(ra + 8) * HF + col]) = v1;
            }
    } else {
        if (fs == 0 && tid4 == 0) {
#pragma unroll
            for (int q = 0; q < 4; q++)
                pden[((size_t)js * HH + head) * NN + i0 + rbase + q * 8] = dacc[q];
        }
        float* pb = pnum + (size_t)js * NN * HF;
#pragma unroll
        for (int mf = 0; mf < 2; mf++)
#pragma unroll
            for (int nf = 0; nf < NFRAG; nf++) {
                int col = head * F + fofs + nf * 8 + tid4 * 2;
                int ra = i0 + rbase + mf * 16;
                float2 v0 = make_float2(acc[mf][nf][0], acc[mf][nf][1]);
                float2 v1 = make_float2(acc[mf][nf][2], acc[mf][nf][3]);
                *reinterpret_cast<float2*>(&pb[(size_t)ra * HF + col]) = v0;
                *reinterpret_cast<float2*>(&pb[(size_t)(ra + 8) * HF + col]) = v1;
            }
    }
}

// combine j-split partials: v = sum(pnum)/sum(pden).
template<int F, int JS, bool SPLITOUT>
__global__ void combine_k(const float* __restrict__ p, const float* __restrict__ dp,
                          float* __restrict__ out, unsigned* __restrict__ ohi,
                          unsigned* __restrict__ olo) {
    constexpr int HF = HH * F;
    int n = blockIdx.x;
    for (int c = threadIdx.x; c < HF; c += blockDim.x) {
        int head = c / F;
        float d = 0.f, v = 0.f;
#pragma unroll
        for (int z = 0; z < JS; z++) {
            d += dp[((size_t)z * HH + head) * NN + n];
            v += p[(size_t)z * NN * HF + (size_t)n * HF + c];
        }
        v /= d;
        if (SPLITOUT) {
            unsigned h, l;
            split_tf32(v, h, l);
            ohi[(size_t)n * HF + c] = h;
            olo[(size_t)n * HF + c] = l;
        } else {
            out[(size_t)n * HF + c] = v;
        }
    }
}

// ---------------- fused batchnorm (stats + normalize + affine + ELU) ----------------
template<int C>
__global__ void bnfuse_k(const float* __restrict__ y, const float* __restrict__ g,
                         const float* __restrict__ b, float* __restrict__ out) {
    int c = blockIdx.x;
    int t = threadIdx.x;  // 256
    float s = 0.f, q = 0.f;
    for (int r = t; r < NN; r += 256) {
        float v = y[r * C + c];
        s += v; q = fmaf(v, v, q);
    }
    __shared__ float ss[256], qq[256];
    ss[t] = s; qq[t] = q;
    __syncthreads();
#pragma unroll
    for (int o = 128; o > 0; o >>= 1) {
        if (t < o) { ss[t] += ss[t + o]; qq[t] += qq[t + o]; }
        __syncthreads();
    }
    __shared__ float mean_s, rstd_s;
    if (t == 0) {
        float mean = ss[0] / (float)NN;
        float var  = qq[0] / (float)NN - mean * mean;
        mean_s = mean;
        rstd_s = rsqrtf(var + 1e-5f);
    }
    __syncthreads();
    float mean = mean_s, rstd = rstd_s;
    float gc = g[c], bc = b[c];
    for (int r = t; r < NN; r += 256) {
        float v = (y[r * C + c] - mean) * rstd;
        v = fmaf(v, gc, bc);
        out[r * C + c] = v > 0.f ? v : expm1f(v);
    }
}

// ---------------- launch ----------------
extern "C" void kernel_launch(void* const* d_in, const int* in_sizes, int n_in,
                              void* d_out, int out_size) {
    const float* x   = (const float*)d_in[0];
    const int*   adj = (const int*)d_in[1];
    const float* W1  = (const float*)d_in[2];
    const float* a1s = (const float*)d_in[3];
    const float* a1d = (const float*)d_in[4];
    const float* lw1 = (const float*)d_in[5];
    const float* lb1 = (const float*)d_in[6];
    const float* g1  = (const float*)d_in[7];
    const float* be1 = (const float*)d_in[8];
    const float* W2  = (const float*)d_in[9];
    const float* a2s = (const float*)d_in[10];
    const float* a2d = (const float*)d_in[11];
    const float* lw2 = (const float*)d_in[12];
    const float* lb2 = (const float*)d_in[13];
    const float* g2  = (const float*)d_in[14];
    const float* be2 = (const float*)d_in[15];
    float* out = (float*)d_out;

    float *h1, *y1, *x2, *h2, *x3, *y2, *part, *dpart, *cvec;
    float2 *rowc1, *evq1, *rowc2, *evq2;
    unsigned *bitsp, *spAh, *spAl, *spBh, *spBl;
    cudaGetSymbolAddress((void**)&h1,  g_h1);
    cudaGetSymbolAddress((void**)&y1,  g_y1);
    cudaGetSymbolAddress((void**)&x2,  g_x2);
    cudaGetSymbolAddress((void**)&h2,  g_h2);
    cudaGetSymbolAddress((void**)&x3,  g_x3);
    cudaGetSymbolAddress((void**)&y2,  g_y2);
    cudaGetSymbolAddress((void**)&rowc1, g_rowc1);
    cudaGetSymbolAddress((void**)&evq1,  g_evq1);
    cudaGetSymbolAddress((void**)&rowc2, g_rowc2);
    cudaGetSymbolAddress((void**)&evq2,  g_evq2);
    cudaGetSymbolAddress((void**)&part,  g_part);
    cudaGetSymbolAddress((void**)&dpart, g_dpart);
    cudaGetSymbolAddress((void**)&bitsp, g_adjbits);
    cudaGetSymbolAddress((void**)&spAh, g_spAh);
    cudaGetSymbolAddress((void**)&spAl, g_spAl);
    cudaGetSymbolAddress((void**)&spBh, g_spBh);
    cudaGetSymbolAddress((void**)&spBl, g_spBl);
    cudaGetSymbolAddress((void**)&cvec, g_cvec);

    const int gemm3_smem = 2 * (2 * 128 * 36 + 2 * 32 * 68) * 4;   // 108544 B
    const int gemm1_smem = 2 * (128 * 36 + 32 * 68) * 4;           // 54272 B
    cudaFuncSetAttribute(gemm3t_pre_k, cudaFuncAttributeMaxDynamicSharedMemorySize, gemm3_smem);
    cudaFuncSetAttribute(gemm1t_k, cudaFuncAttributeMaxDynamicSharedMemorySize, gemm1_smem);

    // ---- layer 1 GAT ----
    cvec_k<<<(512 * HH + 255) / 256, 256>>>(W1, a1s, a1d, cvec, 512, 128);      // 1
    preround_k<<<(512 * 512) / 256, 256>>>(W1, spBh, 512 * 512);                // 2
    esedx_k<512><<<NN, 128>>>(x, cvec, rowc1, evq1, spAh);                      // 3 (also rounds x)
    gemm1t_k<<<dim3(512 / 64, NN / 128), 256, gemm1_smem>>>(spAh, spBh, h1, NN, 512, 512);  // 4 (profiled)
    pack_adj_k<<<(NN * NN / 32) / 256, 256>>>((const int4*)adj, bitsp);         // 5
    attn_mma_k<128, 64, 2, 2><<<dim3(NN / 128, HH, 4), 128>>>(h1, rowc1, evq1, bitsp, nullptr, part, dpart);  // 6
    combine_k<128, 2, true><<<NN, 256>>>(part, dpart, nullptr, spAh, spAl);     // 7

    // ---- MLP 1 + BN + ELU ----
    presplit_k<<<(512 * 64) / 256, 256>>>(lw1, spBh, spBl, 512 * 64);           // 8
    gemm3t_pre_k<<<dim3(1, NN / 128), 256, gemm3_smem>>>(spAh, spAl, spBh, spBl, lb1, y1, NN, 64, 512);  // 9
    bnfuse_k<64><<<64, 256>>>(y1, g1, be1, x2);                                 // 10

    // ---- layer 2 GAT ----
    gemm_k<128, 64, 16, 8, 4><<<dim3(2, NN / 128), 256>>>(x2, W2, nullptr, h2, NN, 128, 64);  // 11
    esed_k<32><<<NN, 128>>>(h2, a2s, a2d, rowc2, evq2);                         // 12
    attn_mma_k<32, 32, 1, 4><<<dim3(NN / 128, HH, 4), 128>>>(h2, rowc2, evq2, bitsp, nullptr, part, dpart);  // 13
    combine_k<32, 4, false><<<NN, 128>>>(part, dpart, x3, nullptr, nullptr);    // 14

    // ---- MLP 2 + BN + ELU ----
    gemm_k<64, 16, 16, 4, 1><<<dim3(1, NN / 64), 256>>>(x3, lw2, lb2, y2, NN, 16, 128);  // 15
    bnfuse_k<16><<<16, 256>>>(y2, g2, be2, out);                                // 16
}